// round 6
// baseline (speedup 1.0000x reference)
#include <cuda_runtime.h>
#include <cstdint>

// ---------------- problem constants ----------------
#define BB    8
#define TT    2048
#define CC    1024
#define BT    (BB*TT)          // 16384 rows
#define N3    (3*CC)           // 3072
#define N4    (4*CC)           // 4096

// ---------------- scratch (device globals, no allocation) ----------------
__device__ float g_ln1[(size_t)BT*CC];
__device__ float g_K  [(size_t)BT*CC];
__device__ float g_V  [(size_t)BT*CC];
__device__ float g_R  [(size_t)BT*CC];
__device__ float g_X1 [(size_t)BT*CC];
__device__ float g_XN [(size_t)BT*CC];
__device__ float g_H  [(size_t)BT*N4];

// ---------------- LayerNorm: one block per row, 256 thr, 1 float4/thr ----
__global__ void __launch_bounds__(256) ln_kernel(const float* __restrict__ x,
                                                 const float* __restrict__ g,
                                                 const float* __restrict__ b,
                                                 float* __restrict__ out)
{
    const int row  = blockIdx.x;
    const int tid  = threadIdx.x;
    const int lane = tid & 31, wid = tid >> 5;

    const float4* xr = (const float4*)(x + (size_t)row * CC);
    float4 v = xr[tid];
    float s = v.x + v.y + v.z + v.w;
    float q = v.x*v.x + v.y*v.y + v.z*v.z + v.w*v.w;

    #pragma unroll
    for (int o = 16; o > 0; o >>= 1) {
        s += __shfl_xor_sync(0xffffffffu, s, o);
        q += __shfl_xor_sync(0xffffffffu, q, o);
    }
    __shared__ float sh_s[8], sh_q[8];
    if (lane == 0) { sh_s[wid] = s; sh_q[wid] = q; }
    __syncthreads();
    float S = 0.f, Q = 0.f;
    #pragma unroll
    for (int i = 0; i < 8; i++) { S += sh_s[i]; Q += sh_q[i]; }

    const float mean = S * (1.0f / CC);
    float var = Q * (1.0f / CC) - mean * mean;
    var = fmaxf(var, 0.0f);
    const float rstd = rsqrtf(var + 1e-5f);

    float4 gg = ((const float4*)g)[tid];
    float4 bb4 = ((const float4*)b)[tid];
    float4 o4;
    o4.x = (v.x - mean) * rstd * gg.x + bb4.x;
    o4.y = (v.y - mean) * rstd * gg.y + bb4.y;
    o4.z = (v.z - mean) * rstd * gg.z + bb4.z;
    o4.w = (v.w - mean) * rstd * gg.w + bb4.w;
    ((float4*)(out + (size_t)row * CC))[tid] = o4;
}

// ---------------- WKV serial scan, fused x1 = x + r*y ----------------
__global__ void __launch_bounds__(128) wkv_kernel(const float* __restrict__ td,
                                                  const float* __restrict__ tf,
                                                  const float* __restrict__ Kb,
                                                  const float* __restrict__ Vb,
                                                  const float* __restrict__ Rb,
                                                  const float* __restrict__ x,
                                                  float* __restrict__ X1,
                                                  float* __restrict__ state)
{
    const int bidx = blockIdx.x >> 3;                 // batch
    const int c    = ((blockIdx.x & 7) << 7) + threadIdx.x;
    const float w = td[c], u = tf[c];

    float aa = 0.0f, bb = -1e38f;
    size_t base = (size_t)bidx * TT * CC + c;

    for (int t = 0; t < TT; ++t) {
        size_t idx = base + (size_t)t * CC;
        float kk = Kb[idx], vv = Vb[idx];
        // output
        float ww = u + kk;
        float p  = fmaxf(bb, ww);
        float e1 = __expf(bb - p);
        float e2 = __expf(ww - p);
        float y  = (e1 * aa + e2 * vv) / (e1 + e2 + 1e-8f);
        X1[idx] = x[idx] + Rb[idx] * y;
        // state update
        float w2 = w + bb;
        float p2 = fmaxf(w2, kk);
        float q1 = __expf(w2 - p2);
        float q2 = __expf(kk - p2);
        aa = q1 * aa + q2 * vv;
        bb = p2 + __logf(q1 + q2 + 1e-8f);
    }
    state[((size_t)bidx * CC + c) * 2 + 0] = aa;
    state[((size_t)bidx * CC + c) * 2 + 1] = bb;
}

// ---------------- Tiled fp32 SIMT GEMM with fused epilogues --------------
// C = A(MxK, row) @ W(KxN, row). BM=BN=128, BK=16, 256 thr, 8x8 microtile
// (split-tile mapping: rows {ty*4..+3, 64+ty*4..+3}, cols likewise with tx).
// EPI 0: time-mix k/v/r   EPI 1: channel-mix + relu^2   EPI 2: final residual
__device__ __forceinline__ float sigmoidf_(float z) {
    return 1.0f / (1.0f + __expf(-z));
}

template<int EPI>
__global__ void __launch_bounds__(256, 2) gemm_kernel(
    const float* __restrict__ A, const float* __restrict__ Wt,
    int K, int N,
    const float* __restrict__ px,   // EPI0: x ; EPI1/2: X1
    const float* __restrict__ pxn,  // EPI2: XN
    const float* __restrict__ m0,   // tmk / cmk / cmr
    const float* __restrict__ m1,   // tmv
    const float* __restrict__ m2,   // tmr
    float* __restrict__ o0, float* __restrict__ o1, float* __restrict__ o2)
{
    constexpr int BM = 128, BN = 128, BK = 16;
    __shared__ __align__(16) float As[2][BK][BM];
    __shared__ __align__(16) float Bs[2][BK][BN];

    const int tid = threadIdx.x;
    const int tx = tid & 15;
    const int ty = tid >> 4;
    const int bm = blockIdx.y * BM;
    const int bn = blockIdx.x * BN;

    // global->smem load maps (2 float4 per thread per matrix per tile)
    const int ia0 = tid * 2,     ia1 = ia0 + 1;
    const int ar0 = ia0 >> 2,    ac0 = (ia0 & 3) << 2;
    const int ar1 = ia1 >> 2,    ac1 = (ia1 & 3) << 2;
    const int br0 = ia0 >> 5,    bc0 = (ia0 & 31) << 2;
    const int br1 = ia1 >> 5,    bc1 = (ia1 & 31) << 2;

    const float* Abase = A + (size_t)bm * K;
    const float* Wbase = Wt + bn;

    float acc[8][8];
    #pragma unroll
    for (int i = 0; i < 8; i++)
        #pragma unroll
        for (int j = 0; j < 8; j++) acc[i][j] = 0.0f;

    float4 fa0, fa1, fb0, fb1;

    // prologue
    {
        const int k0 = 0;
        fa0 = *(const float4*)(Abase + (size_t)ar0 * K + k0 + ac0);
        fa1 = *(const float4*)(Abase + (size_t)ar1 * K + k0 + ac1);
        fb0 = *(const float4*)(Wbase + (size_t)(k0 + br0) * N + bc0);
        fb1 = *(const float4*)(Wbase + (size_t)(k0 + br1) * N + bc1);
        As[0][ac0 + 0][ar0] = fa0.x; As[0][ac0 + 1][ar0] = fa0.y;
        As[0][ac0 + 2][ar0] = fa0.z; As[0][ac0 + 3][ar0] = fa0.w;
        As[0][ac1 + 0][ar1] = fa1.x; As[0][ac1 + 1][ar1] = fa1.y;
        As[0][ac1 + 2][ar1] = fa1.z; As[0][ac1 + 3][ar1] = fa1.w;
        *(float4*)&Bs[0][br0][bc0] = fb0;
        *(float4*)&Bs[0][br1][bc1] = fb1;
    }
    __syncthreads();

    const int nt = K / BK;
    for (int kt = 0; kt < nt; ++kt) {
        const int buf = kt & 1;
        if (kt + 1 < nt) {
            const int k0 = (kt + 1) * BK;
            fa0 = *(const float4*)(Abase + (size_t)ar0 * K + k0 + ac0);
            fa1 = *(const float4*)(Abase + (size_t)ar1 * K + k0 + ac1);
            fb0 = *(const float4*)(Wbase + (size_t)(k0 + br0) * N + bc0);
            fb1 = *(const float4*)(Wbase + (size_t)(k0 + br1) * N + bc1);
        }
        #pragma unroll
        for (int kk = 0; kk < BK; ++kk) {
            float a[8], bfr[8];
            *(float4*)&a[0]   = *(const float4*)&As[buf][kk][ty * 4];
            *(float4*)&a[4]   = *(const float4*)&As[buf][kk][64 + ty * 4];
            *(float4*)&bfr[0] = *(const float4*)&Bs[buf][kk][tx * 4];
            *(float4*)&bfr[4] = *(const float4*)&Bs[buf][kk][64 + tx * 4];
            #pragma unroll
            for (int i = 0; i < 8; i++)
                #pragma unroll
                for (int j = 0; j < 8; j++)
                    acc[i][j] = fmaf(a[i], bfr[j], acc[i][j]);
        }
        if (kt + 1 < nt) {
            const int nb = buf ^ 1;
            As[nb][ac0 + 0][ar0] = fa0.x; As[nb][ac0 + 1][ar0] = fa0.y;
            As[nb][ac0 + 2][ar0] = fa0.z; As[nb][ac0 + 3][ar0] = fa0.w;
            As[nb][ac1 + 0][ar1] = fa1.x; As[nb][ac1 + 1][ar1] = fa1.y;
            As[nb][ac1 + 2][ar1] = fa1.z; As[nb][ac1 + 3][ar1] = fa1.w;
            *(float4*)&Bs[nb][br0][bc0] = fb0;
            *(float4*)&Bs[nb][br1][bc1] = fb1;
        }
        __syncthreads();
    }

    // ---------------- fused epilogue ----------------
    #pragma unroll
    for (int i = 0; i < 8; i++) {
        const int rloc = (i < 4) ? (ty * 4 + i) : (64 + ty * 4 + (i - 4));
        const int m = bm + rloc;
        const int t = m & (TT - 1);
        int pm;
        if (EPI == 0) pm = (t == 0) ? m : (m - 1);            // x_prev: repeat first
        else          pm = (t == 0) ? (m + (TT - 1)) : (m - 1); // xp: wrap last->front
        #pragma unroll
        for (int j = 0; j < 8; j++) {
            const int cloc = (j < 4) ? (tx * 4 + j) : (64 + tx * 4 + (j - 4));
            const int n = bn + cloc;
            const float v = acc[i][j];
            if (EPI == 0) {
                const int sec = n >> 10;
                const int cc  = n & (CC - 1);
                const float xp = px[(size_t)pm * CC + cc];
                if (sec == 0) {
                    const float mk = m0[cc];
                    o0[(size_t)m * CC + cc] = v * mk + xp * (1.0f - mk);
                } else if (sec == 1) {
                    const float mk = m1[cc];
                    o1[(size_t)m * CC + cc] = v * mk + xp * (1.0f - mk);
                } else {
                    const float mk = m2[cc];
                    o2[(size_t)m * CC + cc] = sigmoidf_(v * mk + xp * (1.0f - mk));
                }
            } else if (EPI == 1) {
                const int cc = n & (CC - 1);
                const float xp = px[(size_t)pm * CC + cc];
                const float mk = m0[cc];
                float km = v * mk + xp * (1.0f - mk);
                km = fmaxf(km, 0.0f);
                o0[(size_t)m * N4 + n] = km * km;
            } else {
                const float xp  = px [(size_t)pm * CC + n];
                const float xnv = pxn[(size_t)m  * CC + n];
                const float mk  = m0[n];
                const float rr  = sigmoidf_(xnv * mk + xp * (1.0f - mk));
                o0[(size_t)m * CC + n] = px[(size_t)m * CC + n] + rr * v;
            }
        }
    }
}

// ---------------- launcher ----------------
extern "C" void kernel_launch(void* const* d_in, const int* in_sizes, int n_in,
                              void* d_out, int out_size)
{
    const float* x    = (const float*)d_in[0];
    const float* td   = (const float*)d_in[1];
    const float* tfst = (const float*)d_in[2];
    const float* W_tm = (const float*)d_in[3];
    const float* g1   = (const float*)d_in[4];
    const float* b1   = (const float*)d_in[5];
    const float* tmk  = (const float*)d_in[6];
    const float* tmv  = (const float*)d_in[7];
    const float* tmr  = (const float*)d_in[8];
    const float* W_cm = (const float*)d_in[9];
    const float* W_cp = (const float*)d_in[10];
    const float* g2   = (const float*)d_in[11];
    const float* b2   = (const float*)d_in[12];
    const float* cmk  = (const float*)d_in[13];
    const float* cmr  = (const float*)d_in[14];
    float* out = (float*)d_out;

    float *ln1, *Kb, *Vb, *Rb, *X1, *XN, *Hb;
    cudaGetSymbolAddress((void**)&ln1, g_ln1);
    cudaGetSymbolAddress((void**)&Kb,  g_K);
    cudaGetSymbolAddress((void**)&Vb,  g_V);
    cudaGetSymbolAddress((void**)&Rb,  g_R);
    cudaGetSymbolAddress((void**)&X1,  g_X1);
    cudaGetSymbolAddress((void**)&XN,  g_XN);
    cudaGetSymbolAddress((void**)&Hb,  g_H);

    // 1) LN1
    ln_kernel<<<BT, 256>>>(x, g1, b1, ln1);

    // 2) GEMM1 (16384x1024x3072) + time-mix epilogue -> K,V,R
    gemm_kernel<0><<<dim3(N3 / 128, BT / 128), 256>>>(
        ln1, W_tm, CC, N3, x, nullptr, tmk, tmv, tmr, Kb, Vb, Rb);

    // 3) WKV scan + residual -> X1, and new_state into d_out tail
    wkv_kernel<<<BB * (CC / 128), 128>>>(td, tfst, Kb, Vb, Rb, x, X1,
                                         out + (size_t)BT * CC);

    // 4) LN2
    ln_kernel<<<BT, 256>>>(X1, g2, b2, XN);

    // 5) GEMM2 (16384x1024x4096) + channel-mix + relu^2 -> H
    gemm_kernel<1><<<dim3(N4 / 128, BT / 128), 256>>>(
        XN, W_cm, CC, N4, X1, nullptr, cmk, nullptr, nullptr,
        Hb, nullptr, nullptr);

    // 6) GEMM3 (16384x4096x1024) + final residual -> d_out
    gemm_kernel<2><<<dim3(CC / 128, BT / 128), 256>>>(
        Hb, W_cp, N4, CC, X1, XN, cmr, nullptr, nullptr,
        out, nullptr, nullptr);
}

// round 7
// speedup vs baseline: 2.4068x; 2.4068x over previous
#include <cuda_runtime.h>
#include <cstdint>

// ---------------- problem constants ----------------
#define BB    8
#define TT    2048
#define CCH   1024
#define BT    (BB*TT)          // 16384 rows
#define N3    (3*CCH)          // 3072
#define N4    (4*CCH)          // 4096

// ---------------- scratch (device globals, no allocation) ----------------
__device__ float g_ln1[(size_t)BT*CCH];
__device__ float g_K  [(size_t)BT*CCH];
__device__ float g_V  [(size_t)BT*CCH];
__device__ float g_R  [(size_t)BT*CCH];
__device__ float g_X1 [(size_t)BT*CCH];
__device__ float g_XN [(size_t)BT*CCH];
__device__ float g_H  [(size_t)BT*N4];
__device__ float g_Wtm[(size_t)CCH*N3];
__device__ float g_Wcm[(size_t)CCH*N4];
__device__ float g_Wcp[(size_t)N4*CCH];

// ---------------- helpers ----------------
__device__ __forceinline__ float tf32r(float x) {
    uint32_t u;
    asm("cvt.rna.tf32.f32 %0, %1;" : "=r"(u) : "f"(x));
    return __uint_as_float(u);
}

__device__ __forceinline__ float sigmoidf_(float z) {
    return 1.0f / (1.0f + __expf(-z));
}

__device__ __forceinline__ void cp16(float* dst, const float* src) {
    uint32_t d = (uint32_t)__cvta_generic_to_shared(dst);
    asm volatile("cp.async.cg.shared.global [%0], [%1], 16;\n"
                 :: "r"(d), "l"(src) : "memory");
}
#define CP_COMMIT() asm volatile("cp.async.commit_group;\n" ::: "memory")
#define CP_WAIT(N)  asm volatile("cp.async.wait_group %0;\n" :: "n"(N) : "memory")

__device__ __forceinline__ void mma_tf32(float* c, const uint32_t* a, const uint32_t* b) {
    asm volatile(
        "mma.sync.aligned.m16n8k8.row.col.f32.tf32.tf32.f32 "
        "{%0,%1,%2,%3}, {%4,%5,%6,%7}, {%8,%9}, {%0,%1,%2,%3};"
        : "+f"(c[0]), "+f"(c[1]), "+f"(c[2]), "+f"(c[3])
        : "r"(a[0]), "r"(a[1]), "r"(a[2]), "r"(a[3]), "r"(b[0]), "r"(b[1]));
}

// ---------------- weight -> tf32-rounded copy ----------------
__global__ void __launch_bounds__(256) cvt_kernel(const float4* __restrict__ in,
                                                  float4* __restrict__ out, int n4)
{
    int i = blockIdx.x * 256 + threadIdx.x;
    if (i < n4) {
        float4 v = in[i];
        v.x = tf32r(v.x); v.y = tf32r(v.y); v.z = tf32r(v.z); v.w = tf32r(v.w);
        out[i] = v;
    }
}

// ---------------- LayerNorm (tf32-rounded output) ----------------
__global__ void __launch_bounds__(256) ln_kernel(const float* __restrict__ x,
                                                 const float* __restrict__ g,
                                                 const float* __restrict__ b,
                                                 float* __restrict__ out)
{
    const int row  = blockIdx.x;
    const int tid  = threadIdx.x;
    const int lane = tid & 31, wid = tid >> 5;

    const float4* xr = (const float4*)(x + (size_t)row * CCH);
    float4 v = xr[tid];
    float s = v.x + v.y + v.z + v.w;
    float q = v.x*v.x + v.y*v.y + v.z*v.z + v.w*v.w;

    #pragma unroll
    for (int o = 16; o > 0; o >>= 1) {
        s += __shfl_xor_sync(0xffffffffu, s, o);
        q += __shfl_xor_sync(0xffffffffu, q, o);
    }
    __shared__ float sh_s[8], sh_q[8];
    if (lane == 0) { sh_s[wid] = s; sh_q[wid] = q; }
    __syncthreads();
    float S = 0.f, Q = 0.f;
    #pragma unroll
    for (int i = 0; i < 8; i++) { S += sh_s[i]; Q += sh_q[i]; }

    const float mean = S * (1.0f / CCH);
    float var = Q * (1.0f / CCH) - mean * mean;
    var = fmaxf(var, 0.0f);
    const float rstd = rsqrtf(var + 1e-5f);

    float4 gg = ((const float4*)g)[tid];
    float4 bb4 = ((const float4*)b)[tid];
    float4 o4;
    o4.x = tf32r((v.x - mean) * rstd * gg.x + bb4.x);
    o4.y = tf32r((v.y - mean) * rstd * gg.y + bb4.y);
    o4.z = tf32r((v.z - mean) * rstd * gg.z + bb4.z);
    o4.w = tf32r((v.w - mean) * rstd * gg.w + bb4.w);
    ((float4*)(out + (size_t)row * CCH))[tid] = o4;
}

// ---------------- WKV serial scan, fused x1 = x + r*y ----------------
__global__ void __launch_bounds__(32) wkv_kernel(const float* __restrict__ td,
                                                 const float* __restrict__ tf,
                                                 const float* __restrict__ Kb,
                                                 const float* __restrict__ Vb,
                                                 const float* __restrict__ Rb,
                                                 const float* __restrict__ x,
                                                 float* __restrict__ X1,
                                                 float* __restrict__ state)
{
    const int bidx = blockIdx.x >> 5;
    const int c    = ((blockIdx.x & 31) << 5) + threadIdx.x;
    const float w = td[c], u = tf[c];

    float aa = 0.0f, bb = -1e38f;
    size_t idx = (size_t)bidx * TT * CCH + c;

    float kk = Kb[idx], vv = Vb[idx], rr = Rb[idx], xx = x[idx];
    for (int t = 0; t < TT; ++t) {
        size_t nidx = idx + CCH;
        float kn = 0.f, vn = 0.f, rn = 0.f, xn2 = 0.f;
        if (t + 1 < TT) { kn = Kb[nidx]; vn = Vb[nidx]; rn = Rb[nidx]; xn2 = x[nidx]; }
        // output
        float ww = u + kk;
        float p  = fmaxf(bb, ww);
        float e1 = __expf(bb - p);
        float e2 = __expf(ww - p);
        float y  = (e1 * aa + e2 * vv) / (e1 + e2 + 1e-8f);
        X1[idx] = xx + rr * y;
        // state update
        float w2 = w + bb;
        float p2 = fmaxf(w2, kk);
        float q1 = __expf(w2 - p2);
        float q2 = __expf(kk - p2);
        aa = q1 * aa + q2 * vv;
        bb = p2 + __logf(q1 + q2 + 1e-8f);
        kk = kn; vv = vn; rr = rn; xx = xn2;
        idx = nidx;
    }
    state[((size_t)bidx * CCH + c) * 2 + 0] = aa;
    state[((size_t)bidx * CCH + c) * 2 + 1] = bb;
}

// ---------------- TF32 tensor-core GEMM with fused epilogues ------------
// C = A(MxK, row, tf32-rounded) @ W(KxN, row, tf32-rounded)
// CTA: 128(M) x 256(N), BK=16, 256 thr, 8 warps (2x4), warp tile 64x64
// 3-stage cp.async pipeline; conflict-free smem (LDA=20, LDB=264).
#define GBM   128
#define GBN   256
#define GBK   16
#define NSTG  3
#define LDA   20
#define LDB   264
#define A_STG (GBM*LDA)
#define B_STG (GBK*LDB)
#define SMEM_BYTES ((NSTG*A_STG + NSTG*B_STG)*4)

template<int EPI>
__global__ void __launch_bounds__(256) gemm_tf32_kernel(
    const float* __restrict__ A, const float* __restrict__ Wt,
    int K, int N,
    const float* __restrict__ px,   // EPI0: x ; EPI1/2: X1
    const float* __restrict__ pxn,  // EPI2: XN
    const float* __restrict__ m0,   // tmk / cmk / cmr
    const float* __restrict__ m1,   // tmv
    const float* __restrict__ m2,   // tmr
    float* __restrict__ o0, float* __restrict__ o1, float* __restrict__ o2)
{
    extern __shared__ float sm[];
    float* As = sm;
    float* Bs = sm + NSTG * A_STG;

    const int tid  = threadIdx.x;
    const int lane = tid & 31;
    const int w    = tid >> 5;
    const int wm   = (w & 1) * 64;
    const int wn   = (w >> 1) * 64;
    const int bm   = blockIdx.y * GBM;
    const int bn   = blockIdx.x * GBN;

    float acc[4][8][4];
    #pragma unroll
    for (int i = 0; i < 4; i++)
        #pragma unroll
        for (int j = 0; j < 8; j++)
            #pragma unroll
            for (int q = 0; q < 4; q++) acc[i][j][q] = 0.0f;

#define LOAD_TILE(st, ktile) do {                                              \
    float* As_ = As + (st) * A_STG;                                            \
    float* Bs_ = Bs + (st) * B_STG;                                            \
    {   int c = tid; int m_ = c >> 2, kq = (c & 3) << 2;                       \
        cp16(As_ + m_*LDA + kq, A + (size_t)(bm+m_)*K + (ktile)*GBK + kq);     \
        c = tid + 256; m_ = c >> 2; kq = (c & 3) << 2;                         \
        cp16(As_ + m_*LDA + kq, A + (size_t)(bm+m_)*K + (ktile)*GBK + kq); }   \
    _Pragma("unroll")                                                          \
    for (int i_ = 0; i_ < 4; ++i_) {                                           \
        int c = tid + i_*256; int kr = c >> 6, nq = (c & 63) << 2;             \
        cp16(Bs_ + kr*LDB + nq, Wt + (size_t)((ktile)*GBK + kr)*N + bn + nq);  \
    }                                                                          \
} while (0)

#define COMPUTE(st) do {                                                       \
    const float* Asb = As + (st)*A_STG + (wm + (lane>>2))*LDA + (lane&3);      \
    const float* Bsb = Bs + (st)*B_STG + (lane&3)*LDB + wn + (lane>>2);        \
    _Pragma("unroll")                                                          \
    for (int ks = 0; ks < 2; ++ks) {                                           \
        uint32_t af[4][4]; uint32_t bf[8][2];                                  \
        _Pragma("unroll")                                                      \
        for (int mt = 0; mt < 4; ++mt) {                                       \
            const float* p = Asb + mt*16*LDA + ks*8;                           \
            af[mt][0] = __float_as_uint(p[0]);                                 \
            af[mt][1] = __float_as_uint(p[8*LDA]);                             \
            af[mt][2] = __float_as_uint(p[4]);                                 \
            af[mt][3] = __float_as_uint(p[8*LDA + 4]);                         \
        }                                                                      \
        _Pragma("unroll")                                                      \
        for (int nt = 0; nt < 8; ++nt) {                                       \
            const float* q = Bsb + ks*8*LDB + nt*8;                            \
            bf[nt][0] = __float_as_uint(q[0]);                                 \
            bf[nt][1] = __float_as_uint(q[4*LDB]);                             \
        }                                                                      \
        _Pragma("unroll")                                                      \
        for (int mt = 0; mt < 4; ++mt)                                         \
            _Pragma("unroll")                                                  \
            for (int nt = 0; nt < 8; ++nt)                                     \
                mma_tf32(acc[mt][nt], af[mt], bf[nt]);                         \
    }                                                                          \
} while (0)

    const int ntile = K / GBK;
    LOAD_TILE(0, 0); CP_COMMIT();
    LOAD_TILE(1, 1); CP_COMMIT();

    for (int kt = 0; kt < ntile; ++kt) {
        CP_WAIT(1);
        __syncthreads();
        const int lt = kt + 2;
        if (lt < ntile) {
            const int ls = lt - (lt / NSTG) * NSTG;
            LOAD_TILE(ls, lt);
        }
        CP_COMMIT();
        const int cs = kt - (kt / NSTG) * NSTG;
        COMPUTE(cs);
    }

#undef LOAD_TILE
#undef COMPUTE

    // ---------------- fused epilogue ----------------
    #pragma unroll
    for (int mt = 0; mt < 4; ++mt) {
        #pragma unroll
        for (int h = 0; h < 2; ++h) {
            const int m = bm + wm + mt*16 + (lane >> 2) + h*8;
            const int t = m & (TT - 1);
            int pm;
            if (EPI == 0) pm = (t == 0) ? m : (m - 1);              // repeat first
            else          pm = (t == 0) ? (m + (TT - 1)) : (m - 1); // wrap last->front
            #pragma unroll
            for (int nt = 0; nt < 8; ++nt) {
                const int n = bn + wn + nt*8 + (lane & 3)*2;
                const float v0 = acc[mt][nt][h*2];
                const float v1 = acc[mt][nt][h*2 + 1];
                if (EPI == 0) {
                    const int sec = n >> 10;
                    const int cc  = n & (CCH - 1);
                    const float xp0 = px[(size_t)pm*CCH + cc];
                    const float xp1 = px[(size_t)pm*CCH + cc + 1];
                    float* dst; const float* mk;
                    if (sec == 0)      { dst = o0; mk = m0; }
                    else if (sec == 1) { dst = o1; mk = m1; }
                    else               { dst = o2; mk = m2; }
                    const float mk0 = mk[cc], mk1 = mk[cc + 1];
                    float r0 = v0 * mk0 + xp0 * (1.0f - mk0);
                    float r1 = v1 * mk1 + xp1 * (1.0f - mk1);
                    if (sec == 2) { r0 = sigmoidf_(r0); r1 = sigmoidf_(r1); }
                    *(float2*)&dst[(size_t)m*CCH + cc] = make_float2(r0, r1);
                } else if (EPI == 1) {
                    const int cc = n & (CCH - 1);
                    const float xp0 = px[(size_t)pm*CCH + cc];
                    const float xp1 = px[(size_t)pm*CCH + cc + 1];
                    const float mk0 = m0[cc], mk1 = m0[cc + 1];
                    float k0 = fmaxf(v0 * mk0 + xp0 * (1.0f - mk0), 0.0f);
                    float k1 = fmaxf(v1 * mk1 + xp1 * (1.0f - mk1), 0.0f);
                    *(float2*)&o0[(size_t)m*N4 + n] =
                        make_float2(tf32r(k0 * k0), tf32r(k1 * k1));
                } else {
                    const float xp0 = px [(size_t)pm*CCH + n];
                    const float xp1 = px [(size_t)pm*CCH + n + 1];
                    const float xn0 = pxn[(size_t)m *CCH + n];
                    const float xn1 = pxn[(size_t)m *CCH + n + 1];
                    const float mk0 = m0[n], mk1 = m0[n + 1];
                    const float rr0 = sigmoidf_(xn0 * mk0 + xp0 * (1.0f - mk0));
                    const float rr1 = sigmoidf_(xn1 * mk1 + xp1 * (1.0f - mk1));
                    const float x0  = px[(size_t)m*CCH + n];
                    const float x1v = px[(size_t)m*CCH + n + 1];
                    *(float2*)&o0[(size_t)m*CCH + n] =
                        make_float2(x0 + rr0 * v0, x1v + rr1 * v1);
                }
            }
        }
    }
}

// ---------------- launcher ----------------
extern "C" void kernel_launch(void* const* d_in, const int* in_sizes, int n_in,
                              void* d_out, int out_size)
{
    const float* x    = (const float*)d_in[0];
    const float* td   = (const float*)d_in[1];
    const float* tfst = (const float*)d_in[2];
    const float* W_tm = (const float*)d_in[3];
    const float* g1   = (const float*)d_in[4];
    const float* b1   = (const float*)d_in[5];
    const float* tmk  = (const float*)d_in[6];
    const float* tmv  = (const float*)d_in[7];
    const float* tmr  = (const float*)d_in[8];
    const float* W_cm = (const float*)d_in[9];
    const float* W_cp = (const float*)d_in[10];
    const float* g2   = (const float*)d_in[11];
    const float* b2   = (const float*)d_in[12];
    const float* cmk  = (const float*)d_in[13];
    const float* cmr  = (const float*)d_in[14];
    float* out = (float*)d_out;

    float *ln1, *Kb, *Vb, *Rb, *X1, *XN, *Hb, *Wtm, *Wcm, *Wcp;
    cudaGetSymbolAddress((void**)&ln1, g_ln1);
    cudaGetSymbolAddress((void**)&Kb,  g_K);
    cudaGetSymbolAddress((void**)&Vb,  g_V);
    cudaGetSymbolAddress((void**)&Rb,  g_R);
    cudaGetSymbolAddress((void**)&X1,  g_X1);
    cudaGetSymbolAddress((void**)&XN,  g_XN);
    cudaGetSymbolAddress((void**)&Hb,  g_H);
    cudaGetSymbolAddress((void**)&Wtm, g_Wtm);
    cudaGetSymbolAddress((void**)&Wcm, g_Wcm);
    cudaGetSymbolAddress((void**)&Wcp, g_Wcp);

    static bool attr_done = false;
    if (!attr_done) {
        cudaFuncSetAttribute(gemm_tf32_kernel<0>,
            cudaFuncAttributeMaxDynamicSharedMemorySize, SMEM_BYTES);
        cudaFuncSetAttribute(gemm_tf32_kernel<1>,
            cudaFuncAttributeMaxDynamicSharedMemorySize, SMEM_BYTES);
        cudaFuncSetAttribute(gemm_tf32_kernel<2>,
            cudaFuncAttributeMaxDynamicSharedMemorySize, SMEM_BYTES);
        attr_done = true;
    }

    // 0) round weights to tf32 (unbiased) into scratch
    {
        int n4a = CCH * N3 / 4, n4b = CCH * N4 / 4, n4c = N4 * CCH / 4;
        cvt_kernel<<<(n4a + 255) / 256, 256>>>((const float4*)W_tm, (float4*)Wtm, n4a);
        cvt_kernel<<<(n4b + 255) / 256, 256>>>((const float4*)W_cm, (float4*)Wcm, n4b);
        cvt_kernel<<<(n4c + 255) / 256, 256>>>((const float4*)W_cp, (float4*)Wcp, n4c);
    }

    // 1) LN1 (tf32-rounded output)
    ln_kernel<<<BT, 256>>>(x, g1, b1, ln1);

    // 2) GEMM1 (16384x1024x3072) + time-mix epilogue -> K,V,R
    gemm_tf32_kernel<0><<<dim3(N3 / GBN, BT / GBM), 256, SMEM_BYTES>>>(
        ln1, Wtm, CCH, N3, x, nullptr, tmk, tmv, tmr, Kb, Vb, Rb);

    // 3) WKV scan + residual -> X1, new_state into d_out tail
    wkv_kernel<<<BB * (CCH / 32), 32>>>(td, tfst, Kb, Vb, Rb, x, X1,
                                        out + (size_t)BT * CCH);

    // 4) LN2 (tf32-rounded output)
    ln_kernel<<<BT, 256>>>(X1, g2, b2, XN);

    // 5) GEMM2 (16384x1024x4096) + channel-mix + relu^2 -> H (tf32-rounded)
    gemm_tf32_kernel<1><<<dim3(N4 / GBN, BT / GBM), 256, SMEM_BYTES>>>(
        XN, Wcm, CCH, N4, X1, nullptr, cmk, nullptr, nullptr,
        Hb, nullptr, nullptr);

    // 6) GEMM3 (16384x4096x1024) + final residual -> d_out
    gemm_tf32_kernel<2><<<dim3(CCH / GBN, BT / GBM), 256, SMEM_BYTES>>>(
        Hb, Wcp, N4, CCH, X1, XN, cmr, nullptr, nullptr,
        out, nullptr, nullptr);
}

// round 9
// speedup vs baseline: 3.2533x; 1.3517x over previous
#include <cuda_runtime.h>
#include <cuda_fp16.h>
#include <cstdint>

// ---------------- problem constants ----------------
#define BB    8
#define TT    2048
#define CCH   1024
#define BT    (BB*TT)          // 16384 rows
#define N3    (3*CCH)          // 3072
#define N4    (4*CCH)          // 4096

// ---------------- scratch (device globals, no allocation) ----------------
__device__ __half g_ln1h[(size_t)BT*CCH];
__device__ float  g_K  [(size_t)BT*CCH];
__device__ float  g_V  [(size_t)BT*CCH];
__device__ float  g_R  [(size_t)BT*CCH];
__device__ float  g_X1 [(size_t)BT*CCH];
__device__ float  g_XN [(size_t)BT*CCH];
__device__ __half g_XNh[(size_t)BT*CCH];
__device__ __half g_Hh [(size_t)BT*N4];
__device__ __half g_Wtm[(size_t)CCH*N3];   // transposed: (3C, C) half
__device__ __half g_Wcm[(size_t)CCH*N4];   // transposed: (4C, C) half
__device__ __half g_Wcp[(size_t)N4*CCH];   // transposed: (C, 4C) half

// ---------------- helpers ----------------
__device__ __forceinline__ float sigmoidf_(float z) {
    return 1.0f / (1.0f + __expf(-z));
}
__device__ __forceinline__ void cp16s(uint32_t dst, const void* src) {
    asm volatile("cp.async.cg.shared.global [%0], [%1], 16;\n"
                 :: "r"(dst), "l"(src) : "memory");
}
#define CP_COMMIT() asm volatile("cp.async.commit_group;\n" ::: "memory")
#define CP_WAIT(Ng) asm volatile("cp.async.wait_group %0;\n" :: "n"(Ng) : "memory")

__device__ __forceinline__ void mma_f16(float* c, const uint32_t* a, const uint32_t* b) {
    asm volatile(
        "mma.sync.aligned.m16n8k16.row.col.f32.f16.f16.f32 "
        "{%0,%1,%2,%3}, {%4,%5,%6,%7}, {%8,%9}, {%0,%1,%2,%3};"
        : "+f"(c[0]), "+f"(c[1]), "+f"(c[2]), "+f"(c[3])
        : "r"(a[0]), "r"(a[1]), "r"(a[2]), "r"(a[3]), "r"(b[0]), "r"(b[1]));
}

// ---------------- transpose + fp16 convert (W K x N -> Wt N x K) ----------
__global__ void __launch_bounds__(256) transpose_h(const float* __restrict__ in,
                                                   __half* __restrict__ out,
                                                   int Kd, int Nd)
{
    __shared__ float tile[32][33];
    const int bx = blockIdx.x * 32;   // N
    const int by = blockIdx.y * 32;   // K
    const int tx = threadIdx.x, ty = threadIdx.y;
    #pragma unroll
    for (int i = 0; i < 32; i += 8)
        tile[ty + i][tx] = in[(size_t)(by + ty + i) * Nd + bx + tx];
    __syncthreads();
    #pragma unroll
    for (int i = 0; i < 32; i += 8)
        out[(size_t)(bx + ty + i) * Kd + by + tx] = __float2half_rn(tile[tx][ty + i]);
}

// ---------------- LayerNorm: half output (+ optional fp32 copy) -----------
__global__ void __launch_bounds__(256) ln_kernel(const float* __restrict__ x,
                                                 const float* __restrict__ g,
                                                 const float* __restrict__ b,
                                                 __half* __restrict__ outh,
                                                 float* __restrict__ outf)
{
    const int row  = blockIdx.x;
    const int tid  = threadIdx.x;
    const int lane = tid & 31, wid = tid >> 5;

    const float4* xr = (const float4*)(x + (size_t)row * CCH);
    float4 v = xr[tid];
    float s = v.x + v.y + v.z + v.w;
    float q = v.x*v.x + v.y*v.y + v.z*v.z + v.w*v.w;

    #pragma unroll
    for (int o = 16; o > 0; o >>= 1) {
        s += __shfl_xor_sync(0xffffffffu, s, o);
        q += __shfl_xor_sync(0xffffffffu, q, o);
    }
    __shared__ float sh_s[8], sh_q[8];
    if (lane == 0) { sh_s[wid] = s; sh_q[wid] = q; }
    __syncthreads();
    float S = 0.f, Q = 0.f;
    #pragma unroll
    for (int i = 0; i < 8; i++) { S += sh_s[i]; Q += sh_q[i]; }

    const float mean = S * (1.0f / CCH);
    float var = Q * (1.0f / CCH) - mean * mean;
    var = fmaxf(var, 0.0f);
    const float rstd = rsqrtf(var + 1e-5f);

    float4 gg = ((const float4*)g)[tid];
    float4 bb4 = ((const float4*)b)[tid];
    float4 o4;
    o4.x = (v.x - mean) * rstd * gg.x + bb4.x;
    o4.y = (v.y - mean) * rstd * gg.y + bb4.y;
    o4.z = (v.z - mean) * rstd * gg.z + bb4.z;
    o4.w = (v.w - mean) * rstd * gg.w + bb4.w;

    __half2 h0 = __floats2half2_rn(o4.x, o4.y);
    __half2 h1 = __floats2half2_rn(o4.z, o4.w);
    uint2 hh; hh.x = *(uint32_t*)&h0; hh.y = *(uint32_t*)&h1;
    ((uint2*)(outh + (size_t)row * CCH))[tid] = hh;
    if (outf) ((float4*)(outf + (size_t)row * CCH))[tid] = o4;
}

// ---------------- WKV serial scan, fused x1 = x + r*y ----------------
__global__ void __launch_bounds__(32) wkv_kernel(const float* __restrict__ td,
                                                 const float* __restrict__ tf,
                                                 const float* __restrict__ Kb,
                                                 const float* __restrict__ Vb,
                                                 const float* __restrict__ Rb,
                                                 const float* __restrict__ x,
                                                 float* __restrict__ X1,
                                                 float* __restrict__ state)
{
    const int bidx = blockIdx.x >> 5;
    const int c    = ((blockIdx.x & 31) << 5) + threadIdx.x;
    const float w = td[c], u = tf[c];

    float aa = 0.0f, bb = -1e38f;
    size_t idx = (size_t)bidx * TT * CCH + c;

    float kk = Kb[idx], vv = Vb[idx], rr = Rb[idx], xx = x[idx];
    for (int t = 0; t < TT; ++t) {
        size_t nidx = idx + CCH;
        float kn = 0.f, vn = 0.f, rn = 0.f, xn2 = 0.f;
        if (t + 1 < TT) { kn = Kb[nidx]; vn = Vb[nidx]; rn = Rb[nidx]; xn2 = x[nidx]; }
        float ww = u + kk;
        float p  = fmaxf(bb, ww);
        float e1 = __expf(bb - p);
        float e2 = __expf(ww - p);
        float y  = (e1 * aa + e2 * vv) / (e1 + e2 + 1e-8f);
        X1[idx] = xx + rr * y;
        float w2 = w + bb;
        float p2 = fmaxf(w2, kk);
        float q1 = __expf(w2 - p2);
        float q2 = __expf(kk - p2);
        aa = q1 * aa + q2 * vv;
        bb = p2 + __logf(q1 + q2 + 1e-8f);
        kk = kn; vv = vn; rr = rn; xx = xn2;
        idx = nidx;
    }
    state[((size_t)bidx * CCH + c) * 2 + 0] = aa;
    state[((size_t)bidx * CCH + c) * 2 + 1] = bb;
}

// ---------------- FP16 mma.sync GEMM with fused epilogues ---------------
// C = A(MxK, row, half) @ Wt(NxK, row, half)^T ; fp32 accumulate.
// CTA: 128(M) x 256(N), BK=32, 256 thr, 8 warps (2x4), warp tile 64x64.
// m16n8k16 grid per warp: 4(m) x 8(n), 2 k-steps per tile.
// smem: As[m][k] pitch 40 halves, Bs[n][k] pitch 40 halves (conflict-free
// fragment loads: bank = (20g + t4) mod 32 is a permutation over the warp).
#define GBK    32
#define LDW    20                      // 32-bit words per smem row (40 halves)
#define STGA   (128*LDW*4)             // 10240 B
#define STGB   (256*LDW*4)             // 20480 B
#define STG    (STGA+STGB)             // 30720 B
#define NSTG   3
#define SMEM_TOT (NSTG*STG)            // 92160 B

#define LOADSTAGE(s_, kt_) do {                                               \
    uint32_t ab_ = smem + (uint32_t)(s_) * STG;                               \
    uint32_t bb_ = ab_ + STGA;                                                \
    _Pragma("unroll")                                                         \
    for (int i_ = 0; i_ < 2; i_++) {                                          \
        int idx_ = tid + i_*256; int r_ = idx_ >> 2; int c_ = idx_ & 3;       \
        cp16s(ab_ + r_*80 + c_*16, A + (size_t)(bm+r_)*K + (kt_)*GBK + c_*8); \
    }                                                                         \
    _Pragma("unroll")                                                         \
    for (int i_ = 0; i_ < 4; i_++) {                                          \
        int idx_ = tid + i_*256; int r_ = idx_ >> 2; int c_ = idx_ & 3;       \
        cp16s(bb_ + r_*80 + c_*16, Wt + (size_t)(bn+r_)*K + (kt_)*GBK + c_*8);\
    }                                                                         \
} while (0)

#define COMPUTE(st_) do {                                                     \
    const uint32_t* Aw = (const uint32_t*)(dsm + (st_)*STG);                  \
    const uint32_t* Bw = (const uint32_t*)(dsm + (st_)*STG + STGA);           \
    _Pragma("unroll")                                                         \
    for (int ks = 0; ks < 2; ++ks) {                                          \
        uint32_t af[4][4]; uint32_t bf[8][2];                                 \
        _Pragma("unroll")                                                     \
        for (int mt = 0; mt < 4; ++mt) {                                      \
            int base = (wm + mt*16 + gq)*LDW + ks*8 + t4;                     \
            af[mt][0] = Aw[base];       af[mt][1] = Aw[base + 8*LDW];         \
            af[mt][2] = Aw[base + 4];   af[mt][3] = Aw[base + 8*LDW + 4];     \
        }                                                                     \
        _Pragma("unroll")                                                     \
        for (int nt = 0; nt < 8; ++nt) {                                      \
            int base = (wn + nt*8 + gq)*LDW + ks*8 + t4;                      \
            bf[nt][0] = Bw[base];       bf[nt][1] = Bw[base + 4];             \
        }                                                                     \
        _Pragma("unroll")                                                     \
        for (int mt = 0; mt < 4; ++mt)                                        \
            _Pragma("unroll")                                                 \
            for (int nt = 0; nt < 8; ++nt)                                    \
                mma_f16(acc[mt][nt], af[mt], bf[nt]);                         \
    }                                                                         \
} while (0)

template<int EPI>
__global__ void __launch_bounds__(256) gemm_f16_kernel(
    const __half* __restrict__ A, const __half* __restrict__ Wt,
    int K, int N,
    const float* __restrict__ px,   // EPI0: x ; EPI1/2: X1
    const float* __restrict__ pxn,  // EPI2: XN (fp32)
    const float* __restrict__ m0,   // tmk / cmk / cmr
    const float* __restrict__ m1,   // tmv
    const float* __restrict__ m2,   // tmr
    float* __restrict__ o0, float* __restrict__ o1, float* __restrict__ o2)
{
    extern __shared__ char dsm[];

    const int tid  = threadIdx.x;
    const int lane = tid & 31;
    const int w    = tid >> 5;
    const int gq   = lane >> 2;
    const int t4   = lane & 3;
    const int wm   = (w & 1) * 64;
    const int wn   = (w >> 1) * 64;
    const int bm   = blockIdx.y * 128;
    const int bn   = blockIdx.x * 256;
    const uint32_t smem = (uint32_t)__cvta_generic_to_shared(dsm);

    float acc[4][8][4];
    #pragma unroll
    for (int i = 0; i < 4; i++)
        #pragma unroll
        for (int j = 0; j < 8; j++)
            #pragma unroll
            for (int q = 0; q < 4; q++) acc[i][j][q] = 0.0f;

    const int nt_ = K / GBK;
    LOADSTAGE(0, 0); CP_COMMIT();
    LOADSTAGE(1, 1); CP_COMMIT();

    for (int kt = 0; kt < nt_; ++kt) {
        CP_WAIT(1);
        __syncthreads();
        const int lt = kt + 2;
        if (lt < nt_) {
            const int ls = lt - (lt / NSTG) * NSTG;
            LOADSTAGE(ls, lt);
        }
        CP_COMMIT();
        const int cs = kt - (kt / NSTG) * NSTG;
        COMPUTE(cs);
        __syncthreads();
    }

#undef LOADSTAGE
#undef COMPUTE

    // ---------------- fused epilogue ----------------
    #pragma unroll
    for (int mt = 0; mt < 4; ++mt) {
        #pragma unroll
        for (int h = 0; h < 2; ++h) {
            const int m = bm + wm + mt*16 + gq + h*8;
            const int t = m & (TT - 1);
            int pm;
            if (EPI == 0) pm = (t == 0) ? m : (m - 1);              // repeat first
            else          pm = (t == 0) ? (m + (TT - 1)) : (m - 1); // wrap last->front
            #pragma unroll
            for (int nt2 = 0; nt2 < 8; ++nt2) {
                const int n = bn + wn + nt2*8 + t4*2;
                const float v0 = acc[mt][nt2][h*2];
                const float v1 = acc[mt][nt2][h*2 + 1];
                if (EPI == 0) {
                    const int sec = n >> 10;
                    const int cc  = n & (CCH - 1);
                    const float xp0 = px[(size_t)pm*CCH + cc];
                    const float xp1 = px[(size_t)pm*CCH + cc + 1];
                    float* dst; const float* mk;
                    if (sec == 0)      { dst = o0; mk = m0; }
                    else if (sec == 1) { dst = o1; mk = m1; }
                    else               { dst = o2; mk = m2; }
                    const float mk0 = mk[cc], mk1 = mk[cc + 1];
                    float r0 = v0 * mk0 + xp0 * (1.0f - mk0);
                    float r1 = v1 * mk1 + xp1 * (1.0f - mk1);
                    if (sec == 2) { r0 = sigmoidf_(r0); r1 = sigmoidf_(r1); }
                    *(float2*)&dst[(size_t)m*CCH + cc] = make_float2(r0, r1);
                } else if (EPI == 1) {
                    const int cc = n & (CCH - 1);
                    const float xp0 = px[(size_t)pm*CCH + cc];
                    const float xp1 = px[(size_t)pm*CCH + cc + 1];
                    const float mk0 = m0[cc], mk1 = m0[cc + 1];
                    float k0 = fmaxf(v0 * mk0 + xp0 * (1.0f - mk0), 0.0f);
                    float k1 = fmaxf(v1 * mk1 + xp1 * (1.0f - mk1), 0.0f);
                    __half2 hv = __floats2half2_rn(k0 * k0, k1 * k1);
                    *(__half2*)&((__half*)o0)[(size_t)m*N + n] = hv;
                } else {
                    const float xp0 = px [(size_t)pm*CCH + n];
                    const float xp1 = px [(size_t)pm*CCH + n + 1];
                    const float xn0 = pxn[(size_t)m *CCH + n];
                    const float xn1 = pxn[(size_t)m *CCH + n + 1];
                    const float mk0 = m0[n], mk1 = m0[n + 1];
                    const float rr0 = sigmoidf_(xn0 * mk0 + xp0 * (1.0f - mk0));
                    const float rr1 = sigmoidf_(xn1 * mk1 + xp1 * (1.0f - mk1));
                    const float x0  = px[(size_t)m*CCH + n];
                    const float x1v = px[(size_t)m*CCH + n + 1];
                    *(float2*)&o0[(size_t)m*CCH + n] =
                        make_float2(x0 + rr0 * v0, x1v + rr1 * v1);
                }
            }
        }
    }
}

// ---------------- launcher ----------------
extern "C" void kernel_launch(void* const* d_in, const int* in_sizes, int n_in,
                              void* d_out, int out_size)
{
    const float* x    = (const float*)d_in[0];
    const float* td   = (const float*)d_in[1];
    const float* tfst = (const float*)d_in[2];
    const float* W_tm = (const float*)d_in[3];
    const float* g1   = (const float*)d_in[4];
    const float* b1   = (const float*)d_in[5];
    const float* tmk  = (const float*)d_in[6];
    const float* tmv  = (const float*)d_in[7];
    const float* tmr  = (const float*)d_in[8];
    const float* W_cm = (const float*)d_in[9];
    const float* W_cp = (const float*)d_in[10];
    const float* g2   = (const float*)d_in[11];
    const float* b2   = (const float*)d_in[12];
    const float* cmk  = (const float*)d_in[13];
    const float* cmr  = (const float*)d_in[14];
    float* out = (float*)d_out;

    __half *ln1h, *XNh, *Hh, *Wtm, *Wcm, *Wcp;
    float *Kb, *Vb, *Rb, *X1, *XN;
    cudaGetSymbolAddress((void**)&ln1h, g_ln1h);
    cudaGetSymbolAddress((void**)&Kb,  g_K);
    cudaGetSymbolAddress((void**)&Vb,  g_V);
    cudaGetSymbolAddress((void**)&Rb,  g_R);
    cudaGetSymbolAddress((void**)&X1,  g_X1);
    cudaGetSymbolAddress((void**)&XN,  g_XN);
    cudaGetSymbolAddress((void**)&XNh, g_XNh);
    cudaGetSymbolAddress((void**)&Hh,  g_Hh);
    cudaGetSymbolAddress((void**)&Wtm, g_Wtm);
    cudaGetSymbolAddress((void**)&Wcm, g_Wcm);
    cudaGetSymbolAddress((void**)&Wcp, g_Wcp);

    static bool attr_done = false;
    if (!attr_done) {
        cudaFuncSetAttribute(gemm_f16_kernel<0>,
            cudaFuncAttributeMaxDynamicSharedMemorySize, SMEM_TOT);
        cudaFuncSetAttribute(gemm_f16_kernel<1>,
            cudaFuncAttributeMaxDynamicSharedMemorySize, SMEM_TOT);
        cudaFuncSetAttribute(gemm_f16_kernel<2>,
            cudaFuncAttributeMaxDynamicSharedMemorySize, SMEM_TOT);
        attr_done = true;
    }

    // 0) transpose + fp16-convert weights: W(K,N) -> Wt(N,K)
    transpose_h<<<dim3(N3/32,  CCH/32), dim3(32,8)>>>(W_tm, Wtm, CCH, N3);
    transpose_h<<<dim3(N4/32,  CCH/32), dim3(32,8)>>>(W_cm, Wcm, CCH, N4);
    transpose_h<<<dim3(CCH/32, N4/32),  dim3(32,8)>>>(W_cp, Wcp, N4, CCH);

    // 1) LN1 -> half
    ln_kernel<<<BT, 256>>>(x, g1, b1, ln1h, nullptr);

    // 2) GEMM1 (16384x1024x3072) + time-mix epilogue -> K,V,R (fp32)
    gemm_f16_kernel<0><<<dim3(N3/256, BT/128), 256, SMEM_TOT>>>(
        ln1h, Wtm, CCH, N3, x, nullptr, tmk, tmv, tmr, Kb, Vb, Rb);

    // 3) WKV scan + residual -> X1, new_state into d_out tail
    wkv_kernel<<<BB * (CCH/32), 32>>>(td, tfst, Kb, Vb, Rb, x, X1,
                                      out + (size_t)BT * CCH);

    // 4) LN2 -> half (GEMM input) + fp32 (final epilogue)
    ln_kernel<<<BT, 256>>>(X1, g2, b2, XNh, XN);

    // 5) GEMM2 (16384x1024x4096) + channel-mix + relu^2 -> H (half)
    gemm_f16_kernel<1><<<dim3(N4/256, BT/128), 256, SMEM_TOT>>>(
        XNh, Wcm, CCH, N4, X1, nullptr, cmk, nullptr, nullptr,
        (float*)Hh, nullptr, nullptr);

    // 6) GEMM3 (16384x4096x1024) + final residual -> d_out
    gemm_f16_kernel<2><<<dim3(CCH/256, BT/128), 256, SMEM_TOT>>>(
        Hh, Wcp, N4, CCH, X1, XN, cmr, nullptr, nullptr,
        out, nullptr, nullptr);
}

// round 10
// speedup vs baseline: 3.3750x; 1.0374x over previous
#include <cuda_runtime.h>
#include <cuda_fp16.h>
#include <cstdint>

// ---------------- problem constants ----------------
#define BB    8
#define TT    2048
#define CCH   1024
#define BT    (BB*TT)          // 16384 rows
#define N3    (3*CCH)          // 3072
#define N4    (4*CCH)          // 4096

// ---------------- scratch (device globals, no allocation) ----------------
__device__ __half g_ln1h[(size_t)BT*CCH];
__device__ float  g_K  [(size_t)BT*CCH];
__device__ float  g_V  [(size_t)BT*CCH];
__device__ float  g_R  [(size_t)BT*CCH];
__device__ float  g_X1 [(size_t)BT*CCH];
__device__ float  g_XN [(size_t)BT*CCH];
__device__ __half g_XNh[(size_t)BT*CCH];
__device__ __half g_Hh [(size_t)BT*N4];
__device__ __half g_Wtm[(size_t)CCH*N3];   // transposed: (3C, C) half
__device__ __half g_Wcm[(size_t)CCH*N4];   // transposed: (4C, C) half
__device__ __half g_Wcp[(size_t)N4*CCH];   // transposed: (C, 4C) half

// ---------------- helpers ----------------
__device__ __forceinline__ float sigmoidf_(float z) {
    return 1.0f / (1.0f + __expf(-z));
}
__device__ __forceinline__ void cp16s(uint32_t dst, const void* src) {
    asm volatile("cp.async.cg.shared.global [%0], [%1], 16;\n"
                 :: "r"(dst), "l"(src) : "memory");
}
#define CP_COMMIT() asm volatile("cp.async.commit_group;\n" ::: "memory")
#define CP_WAIT(Ng) asm volatile("cp.async.wait_group %0;\n" :: "n"(Ng) : "memory")

__device__ __forceinline__ void mma_f16(float* c, const uint32_t* a, const uint32_t* b) {
    asm volatile(
        "mma.sync.aligned.m16n8k16.row.col.f32.f16.f16.f32 "
        "{%0,%1,%2,%3}, {%4,%5,%6,%7}, {%8,%9}, {%0,%1,%2,%3};"
        : "+f"(c[0]), "+f"(c[1]), "+f"(c[2]), "+f"(c[3])
        : "r"(a[0]), "r"(a[1]), "r"(a[2]), "r"(a[3]), "r"(b[0]), "r"(b[1]));
}
__device__ __forceinline__ void ldsm4(uint32_t& r0, uint32_t& r1,
                                      uint32_t& r2, uint32_t& r3, uint32_t a) {
    asm volatile("ldmatrix.sync.aligned.m8n8.x4.shared.b16 {%0,%1,%2,%3}, [%4];"
                 : "=r"(r0), "=r"(r1), "=r"(r2), "=r"(r3) : "r"(a));
}

// ---------------- transpose + fp16 convert (W K x N -> Wt N x K) ----------
__global__ void __launch_bounds__(256) transpose_h(const float* __restrict__ in,
                                                   __half* __restrict__ out,
                                                   int Kd, int Nd)
{
    __shared__ float tile[32][33];
    const int bx = blockIdx.x * 32;   // N
    const int by = blockIdx.y * 32;   // K
    const int tx = threadIdx.x, ty = threadIdx.y;
    #pragma unroll
    for (int i = 0; i < 32; i += 8)
        tile[ty + i][tx] = in[(size_t)(by + ty + i) * Nd + bx + tx];
    __syncthreads();
    #pragma unroll
    for (int i = 0; i < 32; i += 8)
        out[(size_t)(bx + ty + i) * Kd + by + tx] = __float2half_rn(tile[tx][ty + i]);
}

// ---------------- LayerNorm: half output (+ optional fp32 copy) -----------
__global__ void __launch_bounds__(256) ln_kernel(const float* __restrict__ x,
                                                 const float* __restrict__ g,
                                                 const float* __restrict__ b,
                                                 __half* __restrict__ outh,
                                                 float* __restrict__ outf)
{
    const int row  = blockIdx.x;
    const int tid  = threadIdx.x;
    const int lane = tid & 31, wid = tid >> 5;

    const float4* xr = (const float4*)(x + (size_t)row * CCH);
    float4 v = xr[tid];
    float s = v.x + v.y + v.z + v.w;
    float q = v.x*v.x + v.y*v.y + v.z*v.z + v.w*v.w;

    #pragma unroll
    for (int o = 16; o > 0; o >>= 1) {
        s += __shfl_xor_sync(0xffffffffu, s, o);
        q += __shfl_xor_sync(0xffffffffu, q, o);
    }
    __shared__ float sh_s[8], sh_q[8];
    if (lane == 0) { sh_s[wid] = s; sh_q[wid] = q; }
    __syncthreads();
    float S = 0.f, Q = 0.f;
    #pragma unroll
    for (int i = 0; i < 8; i++) { S += sh_s[i]; Q += sh_q[i]; }

    const float mean = S * (1.0f / CCH);
    float var = Q * (1.0f / CCH) - mean * mean;
    var = fmaxf(var, 0.0f);
    const float rstd = rsqrtf(var + 1e-5f);

    float4 gg = ((const float4*)g)[tid];
    float4 bb4 = ((const float4*)b)[tid];
    float4 o4;
    o4.x = (v.x - mean) * rstd * gg.x + bb4.x;
    o4.y = (v.y - mean) * rstd * gg.y + bb4.y;
    o4.z = (v.z - mean) * rstd * gg.z + bb4.z;
    o4.w = (v.w - mean) * rstd * gg.w + bb4.w;

    __half2 h0 = __floats2half2_rn(o4.x, o4.y);
    __half2 h1 = __floats2half2_rn(o4.z, o4.w);
    uint2 hh; hh.x = *(uint32_t*)&h0; hh.y = *(uint32_t*)&h1;
    ((uint2*)(outh + (size_t)row * CCH))[tid] = hh;
    if (outf) ((float4*)(outf + (size_t)row * CCH))[tid] = o4;
}

// ---------------- WKV serial scan, fused x1 = x + r*y ----------------
__global__ void __launch_bounds__(32) wkv_kernel(const float* __restrict__ td,
                                                 const float* __restrict__ tf,
                                                 const float* __restrict__ Kb,
                                                 const float* __restrict__ Vb,
                                                 const float* __restrict__ Rb,
                                                 const float* __restrict__ x,
                                                 float* __restrict__ X1,
                                                 float* __restrict__ state)
{
    const int bidx = blockIdx.x >> 5;
    const int c    = ((blockIdx.x & 31) << 5) + threadIdx.x;
    const float w = td[c], u = tf[c];

    float aa = 0.0f, bb = -1e38f;
    size_t idx = (size_t)bidx * TT * CCH + c;

    float kk = Kb[idx], vv = Vb[idx], rr = Rb[idx], xx = x[idx];
    for (int t = 0; t < TT; ++t) {
        size_t nidx = idx + CCH;
        float kn = 0.f, vn = 0.f, rn = 0.f, xn2 = 0.f;
        if (t + 1 < TT) { kn = Kb[nidx]; vn = Vb[nidx]; rn = Rb[nidx]; xn2 = x[nidx]; }
        float ww = u + kk;
        float p  = fmaxf(bb, ww);
        float e1 = __expf(bb - p);
        float e2 = __expf(ww - p);
        float y  = (e1 * aa + e2 * vv) / (e1 + e2 + 1e-8f);
        X1[idx] = xx + rr * y;
        float w2 = w + bb;
        float p2 = fmaxf(w2, kk);
        float q1 = __expf(w2 - p2);
        float q2 = __expf(kk - p2);
        aa = q1 * aa + q2 * vv;
        bb = p2 + __logf(q1 + q2 + 1e-8f);
        kk = kn; vv = vn; rr = rn; xx = xn2;
        idx = nidx;
    }
    state[((size_t)bidx * CCH + c) * 2 + 0] = aa;
    state[((size_t)bidx * CCH + c) * 2 + 1] = bb;
}

// ---------------- FP16 mma.sync GEMM with fused epilogues ---------------
// C = A(MxK, row, half) @ Wt(NxK, row, half)^T ; fp32 accumulate.
// CTA: 128(M) x 256(N), BK=32, 256 thr, 8 warps (2x4), warp tile 64x64.
// ldmatrix.x4 fragment loads (16 per warp per k-tile); 4-stage cp.async
// pipeline with ONE __syncthreads per k-tile.
#define GBK    32
#define LDW    20                      // 32-bit words per smem row (40 halves)
#define ROWB   80                      // bytes per smem row
#define STGA   (128*ROWB)              // 10240 B
#define STGB   (256*ROWB)              // 20480 B
#define STG    (STGA+STGB)             // 30720 B
#define NSTG   4
#define SMEM_TOT (NSTG*STG)            // 122880 B

#define LOADSTAGE(s_, kt_) do {                                               \
    uint32_t ab_ = smem + (uint32_t)(s_) * STG;                               \
    uint32_t bb_ = ab_ + STGA;                                                \
    _Pragma("unroll")                                                         \
    for (int i_ = 0; i_ < 2; i_++) {                                          \
        int idx_ = tid + i_*256; int r_ = idx_ >> 2; int c_ = idx_ & 3;       \
        cp16s(ab_ + r_*ROWB + c_*16, A + (size_t)(bm+r_)*K + (kt_)*GBK + c_*8); \
    }                                                                         \
    _Pragma("unroll")                                                         \
    for (int i_ = 0; i_ < 4; i_++) {                                          \
        int idx_ = tid + i_*256; int r_ = idx_ >> 2; int c_ = idx_ & 3;       \
        cp16s(bb_ + r_*ROWB + c_*16, Wt + (size_t)(bn+r_)*K + (kt_)*GBK + c_*8); \
    }                                                                         \
} while (0)

#define COMPUTE(st_) do {                                                     \
    const uint32_t aB_ = smem + (st_)*STG + (uint32_t)(wm)*ROWB + aLane;      \
    const uint32_t bB_ = smem + (st_)*STG + STGA + (uint32_t)(wn)*ROWB + bLane; \
    _Pragma("unroll")                                                         \
    for (int ks = 0; ks < 2; ++ks) {                                          \
        uint32_t af[4][4]; uint32_t bf[8][2];                                 \
        _Pragma("unroll")                                                     \
        for (int mt = 0; mt < 4; ++mt)                                        \
            ldsm4(af[mt][0], af[mt][1], af[mt][2], af[mt][3],                 \
                  aB_ + mt*16*ROWB + ks*32);                                  \
        _Pragma("unroll")                                                     \
        for (int np = 0; np < 4; ++np)                                        \
            ldsm4(bf[2*np][0], bf[2*np][1], bf[2*np+1][0], bf[2*np+1][1],     \
                  bB_ + np*16*ROWB + ks*32);                                  \
        _Pragma("unroll")                                                     \
        for (int mt = 0; mt < 4; ++mt)                                        \
            _Pragma("unroll")                                                 \
            for (int nt = 0; nt < 8; ++nt)                                    \
                mma_f16(acc[mt][nt], af[mt], bf[nt]);                         \
    }                                                                         \
} while (0)

template<int EPI>
__global__ void __launch_bounds__(256) gemm_f16_kernel(
    const __half* __restrict__ A, const __half* __restrict__ Wt,
    int K, int N,
    const float* __restrict__ px,   // EPI0: x ; EPI1/2: X1
    const float* __restrict__ pxn,  // EPI2: XN (fp32)
    const float* __restrict__ m0,   // tmk / cmk / cmr
    const float* __restrict__ m1,   // tmv
    const float* __restrict__ m2,   // tmr
    float* __restrict__ o0, float* __restrict__ o1, float* __restrict__ o2)
{
    extern __shared__ char dsm[];

    const int tid  = threadIdx.x;
    const int lane = tid & 31;
    const int w    = tid >> 5;
    const int gq   = lane >> 2;
    const int t4   = lane & 3;
    const int wm   = (w & 1) * 64;
    const int wn   = (w >> 1) * 64;
    const int bm   = blockIdx.y * 128;
    const int bn   = blockIdx.x * 256;
    const uint32_t smem = (uint32_t)__cvta_generic_to_shared(dsm);

    // ldmatrix lane address components
    // A frag: lanes 0-15 -> rows 0-15 @k0, lanes 16-31 -> rows 0-15 @k+8
    const uint32_t aLane = (uint32_t)(lane & 15) * ROWB + (uint32_t)(lane >> 4) * 16;
    // B frag: mat0/1 = rows n0..7 @k0/@k8 ; mat2/3 = rows n8..15 @k0/@k8
    const uint32_t bLane = ((uint32_t)(lane & 7) + (uint32_t)(lane >> 4) * 8) * ROWB
                         + (uint32_t)((lane >> 3) & 1) * 16;

    float acc[4][8][4];
    #pragma unroll
    for (int i = 0; i < 4; i++)
        #pragma unroll
        for (int j = 0; j < 8; j++)
            #pragma unroll
            for (int q = 0; q < 4; q++) acc[i][j][q] = 0.0f;

    const int ntk = K / GBK;
    LOADSTAGE(0, 0); CP_COMMIT();
    LOADSTAGE(1, 1); CP_COMMIT();
    LOADSTAGE(2, 2); CP_COMMIT();

    for (int kt = 0; kt < ntk; ++kt) {
        CP_WAIT(2);
        __syncthreads();
        const int lt = kt + 3;
        if (lt < ntk) {
            LOADSTAGE(lt & 3, lt);
        }
        CP_COMMIT();
        COMPUTE(kt & 3);
    }

#undef LOADSTAGE
#undef COMPUTE

    // ---------------- fused epilogue ----------------
    #pragma unroll
    for (int mt = 0; mt < 4; ++mt) {
        #pragma unroll
        for (int h = 0; h < 2; ++h) {
            const int m = bm + wm + mt*16 + gq + h*8;
            const int t = m & (TT - 1);
            int pm;
            if (EPI == 0) pm = (t == 0) ? m : (m - 1);              // repeat first
            else          pm = (t == 0) ? (m + (TT - 1)) : (m - 1); // wrap last->front
            #pragma unroll
            for (int nt2 = 0; nt2 < 8; ++nt2) {
                const int n = bn + wn + nt2*8 + t4*2;
                const float v0 = acc[mt][nt2][h*2];
                const float v1 = acc[mt][nt2][h*2 + 1];
                if (EPI == 0) {
                    const int sec = n >> 10;
                    const int cc  = n & (CCH - 1);
                    const float xp0 = px[(size_t)pm*CCH + cc];
                    const float xp1 = px[(size_t)pm*CCH + cc + 1];
                    float* dst; const float* mk;
                    if (sec == 0)      { dst = o0; mk = m0; }
                    else if (sec == 1) { dst = o1; mk = m1; }
                    else               { dst = o2; mk = m2; }
                    const float mk0 = mk[cc], mk1 = mk[cc + 1];
                    float r0 = v0 * mk0 + xp0 * (1.0f - mk0);
                    float r1 = v1 * mk1 + xp1 * (1.0f - mk1);
                    if (sec == 2) { r0 = sigmoidf_(r0); r1 = sigmoidf_(r1); }
                    *(float2*)&dst[(size_t)m*CCH + cc] = make_float2(r0, r1);
                } else if (EPI == 1) {
                    const int cc = n & (CCH - 1);
                    const float xp0 = px[(size_t)pm*CCH + cc];
                    const float xp1 = px[(size_t)pm*CCH + cc + 1];
                    const float mk0 = m0[cc], mk1 = m0[cc + 1];
                    float k0 = fmaxf(v0 * mk0 + xp0 * (1.0f - mk0), 0.0f);
                    float k1 = fmaxf(v1 * mk1 + xp1 * (1.0f - mk1), 0.0f);
                    __half2 hv = __floats2half2_rn(k0 * k0, k1 * k1);
                    *(__half2*)&((__half*)o0)[(size_t)m*N + n] = hv;
                } else {
                    const float xp0 = px [(size_t)pm*CCH + n];
                    const float xp1 = px [(size_t)pm*CCH + n + 1];
                    const float xn0 = pxn[(size_t)m *CCH + n];
                    const float xn1 = pxn[(size_t)m *CCH + n + 1];
                    const float mk0 = m0[n], mk1 = m0[n + 1];
                    const float rr0 = sigmoidf_(xn0 * mk0 + xp0 * (1.0f - mk0));
                    const float rr1 = sigmoidf_(xn1 * mk1 + xp1 * (1.0f - mk1));
                    const float x0  = px[(size_t)m*CCH + n];
                    const float x1v = px[(size_t)m*CCH + n + 1];
                    *(float2*)&o0[(size_t)m*CCH + n] =
                        make_float2(x0 + rr0 * v0, x1v + rr1 * v1);
                }
            }
        }
    }
}

// ---------------- launcher ----------------
extern "C" void kernel_launch(void* const* d_in, const int* in_sizes, int n_in,
                              void* d_out, int out_size)
{
    const float* x    = (const float*)d_in[0];
    const float* td   = (const float*)d_in[1];
    const float* tfst = (const float*)d_in[2];
    const float* W_tm = (const float*)d_in[3];
    const float* g1   = (const float*)d_in[4];
    const float* b1   = (const float*)d_in[5];
    const float* tmk  = (const float*)d_in[6];
    const float* tmv  = (const float*)d_in[7];
    const float* tmr  = (const float*)d_in[8];
    const float* W_cm = (const float*)d_in[9];
    const float* W_cp = (const float*)d_in[10];
    const float* g2   = (const float*)d_in[11];
    const float* b2   = (const float*)d_in[12];
    const float* cmk  = (const float*)d_in[13];
    const float* cmr  = (const float*)d_in[14];
    float* out = (float*)d_out;

    __half *ln1h, *XNh, *Hh, *Wtm, *Wcm, *Wcp;
    float *Kb, *Vb, *Rb, *X1, *XN;
    cudaGetSymbolAddress((void**)&ln1h, g_ln1h);
    cudaGetSymbolAddress((void**)&Kb,  g_K);
    cudaGetSymbolAddress((void**)&Vb,  g_V);
    cudaGetSymbolAddress((void**)&Rb,  g_R);
    cudaGetSymbolAddress((void**)&X1,  g_X1);
    cudaGetSymbolAddress((void**)&XN,  g_XN);
    cudaGetSymbolAddress((void**)&XNh, g_XNh);
    cudaGetSymbolAddress((void**)&Hh,  g_Hh);
    cudaGetSymbolAddress((void**)&Wtm, g_Wtm);
    cudaGetSymbolAddress((void**)&Wcm, g_Wcm);
    cudaGetSymbolAddress((void**)&Wcp, g_Wcp);

    static bool attr_done = false;
    if (!attr_done) {
        cudaFuncSetAttribute(gemm_f16_kernel<0>,
            cudaFuncAttributeMaxDynamicSharedMemorySize, SMEM_TOT);
        cudaFuncSetAttribute(gemm_f16_kernel<1>,
            cudaFuncAttributeMaxDynamicSharedMemorySize, SMEM_TOT);
        cudaFuncSetAttribute(gemm_f16_kernel<2>,
            cudaFuncAttributeMaxDynamicSharedMemorySize, SMEM_TOT);
        attr_done = true;
    }

    // 0) transpose + fp16-convert weights: W(K,N) -> Wt(N,K)
    transpose_h<<<dim3(N3/32,  CCH/32), dim3(32,8)>>>(W_tm, Wtm, CCH, N3);
    transpose_h<<<dim3(N4/32,  CCH/32), dim3(32,8)>>>(W_cm, Wcm, CCH, N4);
    transpose_h<<<dim3(CCH/32, N4/32),  dim3(32,8)>>>(W_cp, Wcp, N4, CCH);

    // 1) LN1 -> half
    ln_kernel<<<BT, 256>>>(x, g1, b1, ln1h, nullptr);

    // 2) GEMM1 (16384x1024x3072) + time-mix epilogue -> K,V,R (fp32)
    gemm_f16_kernel<0><<<dim3(N3/256, BT/128), 256, SMEM_TOT>>>(
        ln1h, Wtm, CCH, N3, x, nullptr, tmk, tmv, tmr, Kb, Vb, Rb);

    // 3) WKV scan + residual -> X1, new_state into d_out tail
    wkv_kernel<<<BB * (CCH/32), 32>>>(td, tfst, Kb, Vb, Rb, x, X1,
                                      out + (size_t)BT * CCH);

    // 4) LN2 -> half (GEMM input) + fp32 (final epilogue)
    ln_kernel<<<BT, 256>>>(X1, g2, b2, XNh, XN);

    // 5) GEMM2 (16384x1024x4096) + channel-mix + relu^2 -> H (half)
    gemm_f16_kernel<1><<<dim3(N4/256, BT/128), 256, SMEM_TOT>>>(
        XNh, Wcm, CCH, N4, X1, nullptr, cmk, nullptr, nullptr,
        (float*)Hh, nullptr, nullptr);

    // 6) GEMM3 (16384x4096x1024) + final residual -> d_out
    gemm_f16_kernel<2><<<dim3(CCH/256, BT/128), 256, SMEM_TOT>>>(
        Hh, Wcp, N4, CCH, X1, XN, cmr, nullptr, nullptr,
        out, nullptr, nullptr);
}

// round 12
// speedup vs baseline: 4.0486x; 1.1996x over previous
#include <cuda_runtime.h>
#include <cuda_fp16.h>
#include <cstdint>

// ---------------- problem constants ----------------
#define BB    8
#define TT    2048
#define CCH   1024
#define BT    (BB*TT)          // 16384 rows
#define N3    (3*CCH)          // 3072
#define N4    (4*CCH)          // 4096

// ---------------- scratch (device globals, no allocation) ----------------
__device__ __half g_ln1h[(size_t)BT*CCH];
__device__ float  g_K  [(size_t)BT*CCH];
__device__ float  g_V  [(size_t)BT*CCH];
__device__ float  g_R  [(size_t)BT*CCH];
__device__ float  g_X1 [(size_t)BT*CCH];
__device__ float  g_XN [(size_t)BT*CCH];
__device__ __half g_XNh[(size_t)BT*CCH];
__device__ __half g_Hh [(size_t)BT*N4];
__device__ __half g_Wtm[(size_t)CCH*N3];   // transposed: (3C, C) half
__device__ __half g_Wcm[(size_t)CCH*N4];   // transposed: (4C, C) half
__device__ __half g_Wcp[(size_t)N4*CCH];   // transposed: (C, 4C) half

// ---------------- helpers ----------------
__device__ __forceinline__ float sigmoidf_(float z) {
    return 1.0f / (1.0f + __expf(-z));
}
__device__ __forceinline__ void cp16s(uint32_t dst, const void* src) {
    asm volatile("cp.async.cg.shared.global [%0], [%1], 16;\n"
                 :: "r"(dst), "l"(src) : "memory");
}
#define CP_COMMIT() asm volatile("cp.async.commit_group;\n" ::: "memory")
#define CP_WAIT(Ng) asm volatile("cp.async.wait_group %0;\n" :: "n"(Ng) : "memory")

__device__ __forceinline__ void mma_f16(float* c, const uint32_t* a, const uint32_t* b) {
    asm volatile(
        "mma.sync.aligned.m16n8k16.row.col.f32.f16.f16.f32 "
        "{%0,%1,%2,%3}, {%4,%5,%6,%7}, {%8,%9}, {%0,%1,%2,%3};"
        : "+f"(c[0]), "+f"(c[1]), "+f"(c[2]), "+f"(c[3])
        : "r"(a[0]), "r"(a[1]), "r"(a[2]), "r"(a[3]), "r"(b[0]), "r"(b[1]));
}
__device__ __forceinline__ void ldsm4(uint32_t& r0, uint32_t& r1,
                                      uint32_t& r2, uint32_t& r3, uint32_t a) {
    asm volatile("ldmatrix.sync.aligned.m8n8.x4.shared.b16 {%0,%1,%2,%3}, [%4];"
                 : "=r"(r0), "=r"(r1), "=r"(r2), "=r"(r3) : "r"(a));
}

// ---------------- transpose + fp16 convert (W K x N -> Wt N x K) ----------
__global__ void __launch_bounds__(256) transpose_h(const float* __restrict__ in,
                                                   __half* __restrict__ out,
                                                   int Kd, int Nd)
{
    __shared__ float tile[32][33];
    const int bx = blockIdx.x * 32;   // N
    const int by = blockIdx.y * 32;   // K
    const int tx = threadIdx.x, ty = threadIdx.y;
    #pragma unroll
    for (int i = 0; i < 32; i += 8)
        tile[ty + i][tx] = in[(size_t)(by + ty + i) * Nd + bx + tx];
    __syncthreads();
    #pragma unroll
    for (int i = 0; i < 32; i += 8)
        out[(size_t)(bx + ty + i) * Kd + by + tx] = __float2half_rn(tile[tx][ty + i]);
}

// ---------------- LayerNorm: half output (+ optional fp32 copy) -----------
__global__ void __launch_bounds__(256) ln_kernel(const float* __restrict__ x,
                                                 const float* __restrict__ g,
                                                 const float* __restrict__ b,
                                                 __half* __restrict__ outh,
                                                 float* __restrict__ outf)
{
    const int row  = blockIdx.x;
    const int tid  = threadIdx.x;
    const int lane = tid & 31, wid = tid >> 5;

    const float4* xr = (const float4*)(x + (size_t)row * CCH);
    float4 v = xr[tid];
    float s = v.x + v.y + v.z + v.w;
    float q = v.x*v.x + v.y*v.y + v.z*v.z + v.w*v.w;

    #pragma unroll
    for (int o = 16; o > 0; o >>= 1) {
        s += __shfl_xor_sync(0xffffffffu, s, o);
        q += __shfl_xor_sync(0xffffffffu, q, o);
    }
    __shared__ float sh_s[8], sh_q[8];
    if (lane == 0) { sh_s[wid] = s; sh_q[wid] = q; }
    __syncthreads();
    float S = 0.f, Q = 0.f;
    #pragma unroll
    for (int i = 0; i < 8; i++) { S += sh_s[i]; Q += sh_q[i]; }

    const float mean = S * (1.0f / CCH);
    float var = Q * (1.0f / CCH) - mean * mean;
    var = fmaxf(var, 0.0f);
    const float rstd = rsqrtf(var + 1e-5f);

    float4 gg = ((const float4*)g)[tid];
    float4 bb4 = ((const float4*)b)[tid];
    float4 o4;
    o4.x = (v.x - mean) * rstd * gg.x + bb4.x;
    o4.y = (v.y - mean) * rstd * gg.y + bb4.y;
    o4.z = (v.z - mean) * rstd * gg.z + bb4.z;
    o4.w = (v.w - mean) * rstd * gg.w + bb4.w;

    __half2 h0 = __floats2half2_rn(o4.x, o4.y);
    __half2 h1 = __floats2half2_rn(o4.z, o4.w);
    uint2 hh; hh.x = *(uint32_t*)&h0; hh.y = *(uint32_t*)&h1;
    ((uint2*)(outh + (size_t)row * CCH))[tid] = hh;
    if (outf) ((float4*)(outf + (size_t)row * CCH))[tid] = o4;
}

// ---------------- WKV scan: EXACT reference recurrence, short chain -------
// Reference state (aa, bb). Re-parameterize: bt = e^{bb - sigma}. Then,
// exactly (e^{p - sigma} = max(E*bt, e^{k-sigma}) = m):
//   y   = (bt*aa + Eu*ek*v) / (bt + Eu*ek + eps*max(bt, Eu*ek))
//   aa' = (E*bt*aa + ek*v) / m
//   bt' = E*bt + ek + eps*m
// where ek = e^{k - sigma} is OFF the carried chain. Renormalize
// sigma += log(bt), bt = 1 every 8 steps (exponents stay bounded).
__global__ void __launch_bounds__(32) wkv_kernel(const float* __restrict__ td,
                                                 const float* __restrict__ tf,
                                                 const float* __restrict__ Kb,
                                                 const float* __restrict__ Vb,
                                                 const float* __restrict__ Rb,
                                                 const float* __restrict__ x,
                                                 float* __restrict__ X1,
                                                 float* __restrict__ state)
{
    const int bidx = blockIdx.x >> 5;
    const int c    = ((blockIdx.x & 31) << 5) + threadIdx.x;
    const float w = td[c], u = tf[c];
    const float E   = __expf(w);
    const float Eu  = __expf(u);
    const float eps = 1e-8f;

    size_t idx = (size_t)bidx * TT * CCH + c;
    float kk = Kb[idx], vv = Vb[idx], rr = Rb[idx], xx = x[idx];

    float sigma = kk;          // so ek(t=0) = 1 (matches bb after step 0)
    float aa = 0.0f, bt = 0.0f;

    for (int t = 0; t < TT; ++t) {
        size_t nidx = idx + CCH;
        float kn = 0.f, vn = 0.f, rn = 0.f, xn2 = 0.f;
        if (t + 1 < TT) { kn = Kb[nidx]; vn = Vb[nidx]; rn = Rb[nidx]; xn2 = x[nidx]; }

        const float ek  = __expf(kk - sigma);   // off-chain
        const float eku = Eu * ek;
        // ---- output (exact scaled form of reference y-step) ----
        const float mp = fmaxf(bt, eku);
        const float y  = fmaf(bt, aa, eku * vv) / fmaf(eps, mp, bt + eku);
        X1[idx] = xx + rr * y;
        // ---- state update (exact scaled form) ----
        const float Ebt = E * bt;
        const float m   = fmaxf(Ebt, ek);
        aa = fmaf(Ebt, aa, ek * vv) / m;
        bt = fmaf(eps, m, Ebt + ek);

        if ((t & 7) == 7) { sigma += __logf(bt); bt = 1.0f; }

        kk = kn; vv = vn; rr = rn; xx = xn2;
        idx = nidx;
    }
    state[((size_t)bidx * CCH + c) * 2 + 0] = aa;
    state[((size_t)bidx * CCH + c) * 2 + 1] = sigma + __logf(bt);
}

// ---------------- FP16 mma.sync GEMM with fused epilogues ---------------
// C = A(MxK, row, half) @ Wt(NxK, row, half)^T ; fp32 accumulate.
// CTA: 128(M) x BN(N), BK=32, 256 thr, 8 warps (2x4), warp tile 64 x BN/4.
// BN templated (256 or 128) to kill wave quantization per GEMM shape.
#define GBK    32
#define ROWB   80                      // bytes per smem row (40 halves)
#define STGA   (128*ROWB)              // 10240 B
#define NSTG   4

#define LOADSTAGE(s_, kt_) do {                                               \
    uint32_t ab_ = smem + (uint32_t)(s_) * STG_;                              \
    uint32_t bb_ = ab_ + STGA;                                                \
    _Pragma("unroll")                                                         \
    for (int i_ = 0; i_ < 2; i_++) {                                          \
        int idx_ = tid + i_*256; int r_ = idx_ >> 2; int c_ = idx_ & 3;       \
        cp16s(ab_ + r_*ROWB + c_*16, A + (size_t)(bm+r_)*K + (kt_)*GBK + c_*8); \
    }                                                                         \
    _Pragma("unroll")                                                         \
    for (int i_ = 0; i_ < BN/64; i_++) {                                      \
        int idx_ = tid + i_*256; int r_ = idx_ >> 2; int c_ = idx_ & 3;       \
        cp16s(bb_ + r_*ROWB + c_*16, Wt + (size_t)(bn+r_)*K + (kt_)*GBK + c_*8); \
    }                                                                         \
} while (0)

#define COMPUTE(st_) do {                                                     \
    const uint32_t aB_ = smem + (st_)*STG_ + (uint32_t)(wm)*ROWB + aLane;     \
    const uint32_t bB_ = smem + (st_)*STG_ + STGA + (uint32_t)(wn)*ROWB + bLane; \
    _Pragma("unroll")                                                         \
    for (int ks = 0; ks < 2; ++ks) {                                          \
        uint32_t af[4][4]; uint32_t bf[NT][2];                                \
        _Pragma("unroll")                                                     \
        for (int mt = 0; mt < 4; ++mt)                                        \
            ldsm4(af[mt][0], af[mt][1], af[mt][2], af[mt][3],                 \
                  aB_ + mt*16*ROWB + ks*32);                                  \
        _Pragma("unroll")                                                     \
        for (int np = 0; np < NT/2; ++np)                                     \
            ldsm4(bf[2*np][0], bf[2*np][1], bf[2*np+1][0], bf[2*np+1][1],     \
                  bB_ + np*16*ROWB + ks*32);                                  \
        _Pragma("unroll")                                                     \
        for (int mt = 0; mt < 4; ++mt)                                        \
            _Pragma("unroll")                                                 \
            for (int nt = 0; nt < NT; ++nt)                                   \
                mma_f16(acc[mt][nt], af[mt], bf[nt]);                         \
    }                                                                         \
} while (0)

template<int EPI, int BN>
__global__ void __launch_bounds__(256) gemm_f16_kernel(
    const __half* __restrict__ A, const __half* __restrict__ Wt,
    int K, int N,
    const float* __restrict__ px,   // EPI0: x ; EPI1/2: X1
    const float* __restrict__ pxn,  // EPI2: XN (fp32)
    const float* __restrict__ m0,   // tmk / cmk / cmr
    const float* __restrict__ m1,   // tmv
    const float* __restrict__ m2,   // tmr
    float* __restrict__ o0, float* __restrict__ o1, float* __restrict__ o2)
{
    extern __shared__ char dsm[];

    constexpr int BNW  = BN / 4;        // n extent per warp
    constexpr int NT   = BNW / 8;       // n-tiles (8 wide) per warp
    constexpr int STG_ = STGA + BN*ROWB;

    const int tid  = threadIdx.x;
    const int lane = tid & 31;
    const int w    = tid >> 5;
    const int gq   = lane >> 2;
    const int t4   = lane & 3;
    const int wm   = (w & 1) * 64;
    const int wn   = (w >> 1) * BNW;
    const int bm   = blockIdx.y * 128;
    const int bn   = blockIdx.x * BN;
    const uint32_t smem = (uint32_t)__cvta_generic_to_shared(dsm);

    // ldmatrix lane address components
    const uint32_t aLane = (uint32_t)(lane & 15) * ROWB + (uint32_t)(lane >> 4) * 16;
    const uint32_t bLane = ((uint32_t)(lane & 7) + (uint32_t)(lane >> 4) * 8) * ROWB
                         + (uint32_t)((lane >> 3) & 1) * 16;

    float acc[4][NT][4];
    #pragma unroll
    for (int i = 0; i < 4; i++)
        #pragma unroll
        for (int j = 0; j < NT; j++)
            #pragma unroll
            for (int q = 0; q < 4; q++) acc[i][j][q] = 0.0f;

    const int ntk = K / GBK;
    LOADSTAGE(0, 0); CP_COMMIT();
    LOADSTAGE(1, 1); CP_COMMIT();
    LOADSTAGE(2, 2); CP_COMMIT();

    for (int kt = 0; kt < ntk; ++kt) {
        CP_WAIT(2);
        __syncthreads();
        const int lt = kt + 3;
        if (lt < ntk) {
            LOADSTAGE(lt & 3, lt);
        }
        CP_COMMIT();
        COMPUTE(kt & 3);
    }

#undef LOADSTAGE
#undef COMPUTE

    // ---------------- fused epilogue ----------------
    #pragma unroll
    for (int mt = 0; mt < 4; ++mt) {
        #pragma unroll
        for (int h = 0; h < 2; ++h) {
            const int m = bm + wm + mt*16 + gq + h*8;
            const int t = m & (TT - 1);
            int pm;
            if (EPI == 0) pm = (t == 0) ? m : (m - 1);              // repeat first
            else          pm = (t == 0) ? (m + (TT - 1)) : (m - 1); // wrap last->front
            #pragma unroll
            for (int nt2 = 0; nt2 < NT; ++nt2) {
                const int n = bn + wn + nt2*8 + t4*2;
                const float v0 = acc[mt][nt2][h*2];
                const float v1 = acc[mt][nt2][h*2 + 1];
                if (EPI == 0) {
                    const int sec = n >> 10;
                    const int cc  = n & (CCH - 1);
                    const float xp0 = px[(size_t)pm*CCH + cc];
                    const float xp1 = px[(size_t)pm*CCH + cc + 1];
                    float* dst; const float* mk;
                    if (sec == 0)      { dst = o0; mk = m0; }
                    else if (sec == 1) { dst = o1; mk = m1; }
                    else               { dst = o2; mk = m2; }
                    const float mk0 = mk[cc], mk1 = mk[cc + 1];
                    float r0 = v0 * mk0 + xp0 * (1.0f - mk0);
                    float r1 = v1 * mk1 + xp1 * (1.0f - mk1);
                    if (sec == 2) { r0 = sigmoidf_(r0); r1 = sigmoidf_(r1); }
                    *(float2*)&dst[(size_t)m*CCH + cc] = make_float2(r0, r1);
                } else if (EPI == 1) {
                    const int cc = n & (CCH - 1);
                    const float xp0 = px[(size_t)pm*CCH + cc];
                    const float xp1 = px[(size_t)pm*CCH + cc + 1];
                    const float mk0 = m0[cc], mk1 = m0[cc + 1];
                    float k0 = fmaxf(v0 * mk0 + xp0 * (1.0f - mk0), 0.0f);
                    float k1 = fmaxf(v1 * mk1 + xp1 * (1.0f - mk1), 0.0f);
                    __half2 hv = __floats2half2_rn(k0 * k0, k1 * k1);
                    *(__half2*)&((__half*)o0)[(size_t)m*N + n] = hv;
                } else {
                    const float xp0 = px [(size_t)pm*CCH + n];
                    const float xp1 = px [(size_t)pm*CCH + n + 1];
                    const float xn0 = pxn[(size_t)m *CCH + n];
                    const float xn1 = pxn[(size_t)m *CCH + n + 1];
                    const float mk0 = m0[n], mk1 = m0[n + 1];
                    const float rr0 = sigmoidf_(xn0 * mk0 + xp0 * (1.0f - mk0));
                    const float rr1 = sigmoidf_(xn1 * mk1 + xp1 * (1.0f - mk1));
                    const float x0  = px[(size_t)m*CCH + n];
                    const float x1v = px[(size_t)m*CCH + n + 1];
                    *(float2*)&o0[(size_t)m*CCH + n] =
                        make_float2(x0 + rr0 * v0, x1v + rr1 * v1);
                }
            }
        }
    }
}

// ---------------- launcher ----------------
#define SMEM_OF(BN) (NSTG * (STGA + (BN)*ROWB))

extern "C" void kernel_launch(void* const* d_in, const int* in_sizes, int n_in,
                              void* d_out, int out_size)
{
    const float* x    = (const float*)d_in[0];
    const float* td   = (const float*)d_in[1];
    const float* tfst = (const float*)d_in[2];
    const float* W_tm = (const float*)d_in[3];
    const float* g1   = (const float*)d_in[4];
    const float* b1   = (const float*)d_in[5];
    const float* tmk  = (const float*)d_in[6];
    const float* tmv  = (const float*)d_in[7];
    const float* tmr  = (const float*)d_in[8];
    const float* W_cm = (const float*)d_in[9];
    const float* W_cp = (const float*)d_in[10];
    const float* g2   = (const float*)d_in[11];
    const float* b2   = (const float*)d_in[12];
    const float* cmk  = (const float*)d_in[13];
    const float* cmr  = (const float*)d_in[14];
    float* out = (float*)d_out;

    __half *ln1h, *XNh, *Hh, *Wtm, *Wcm, *Wcp;
    float *Kb, *Vb, *Rb, *X1, *XN;
    cudaGetSymbolAddress((void**)&ln1h, g_ln1h);
    cudaGetSymbolAddress((void**)&Kb,  g_K);
    cudaGetSymbolAddress((void**)&Vb,  g_V);
    cudaGetSymbolAddress((void**)&Rb,  g_R);
    cudaGetSymbolAddress((void**)&X1,  g_X1);
    cudaGetSymbolAddress((void**)&XN,  g_XN);
    cudaGetSymbolAddress((void**)&XNh, g_XNh);
    cudaGetSymbolAddress((void**)&Hh,  g_Hh);
    cudaGetSymbolAddress((void**)&Wtm, g_Wtm);
    cudaGetSymbolAddress((void**)&Wcm, g_Wcm);
    cudaGetSymbolAddress((void**)&Wcp, g_Wcp);

    static bool attr_done = false;
    if (!attr_done) {
        cudaFuncSetAttribute(gemm_f16_kernel<0,128>,
            cudaFuncAttributeMaxDynamicSharedMemorySize, SMEM_OF(128));
        cudaFuncSetAttribute(gemm_f16_kernel<1,256>,
            cudaFuncAttributeMaxDynamicSharedMemorySize, SMEM_OF(256));
        cudaFuncSetAttribute(gemm_f16_kernel<2,128>,
            cudaFuncAttributeMaxDynamicSharedMemorySize, SMEM_OF(128));
        attr_done = true;
    }

    // 0) transpose + fp16-convert weights: W(K,N) -> Wt(N,K)
    transpose_h<<<dim3(N3/32,  CCH/32), dim3(32,8)>>>(W_tm, Wtm, CCH, N3);
    transpose_h<<<dim3(N4/32,  CCH/32), dim3(32,8)>>>(W_cm, Wcm, CCH, N4);
    transpose_h<<<dim3(CCH/32, N4/32),  dim3(32,8)>>>(W_cp, Wcp, N4, CCH);

    // 1) LN1 -> half
    ln_kernel<<<BT, 256>>>(x, g1, b1, ln1h, nullptr);

    // 2) GEMM1 (16384x1024x3072) + time-mix epilogue -> K,V,R (fp32)
    //    BN=128: 3072 CTAs -> 20.76 waves (1.2% quantization vs 6% at 256)
    gemm_f16_kernel<0,128><<<dim3(N3/128, BT/128), 256, SMEM_OF(128)>>>(
        ln1h, Wtm, CCH, N3, x, nullptr, tmk, tmv, tmr, Kb, Vb, Rb);

    // 3) WKV scan + residual -> X1, new_state into d_out tail
    wkv_kernel<<<BB * (CCH/32), 32>>>(td, tfst, Kb, Vb, Rb, x, X1,
                                      out + (size_t)BT * CCH);

    // 4) LN2 -> half (GEMM input) + fp32 (final epilogue)
    ln_kernel<<<BT, 256>>>(X1, g2, b2, XNh, XN);

    // 5) GEMM2 (16384x1024x4096) + channel-mix + relu^2 -> H (half)
    gemm_f16_kernel<1,256><<<dim3(N4/256, BT/128), 256, SMEM_OF(256)>>>(
        XNh, Wcm, CCH, N4, X1, nullptr, cmk, nullptr, nullptr,
        (float*)Hh, nullptr, nullptr);

    // 6) GEMM3 (16384x4096x1024) + final residual -> d_out
    //    BN=128: 1024 CTAs -> 6.92 waves (1.2% vs 15.6% at 256)
    gemm_f16_kernel<2,128><<<dim3(CCH/128, BT/128), 256, SMEM_OF(128)>>>(
        Hh, Wcp, N4, CCH, X1, XN, cmr, nullptr, nullptr,
        out, nullptr, nullptr);
}

// round 13
// speedup vs baseline: 5.3398x; 1.3189x over previous
#include <cuda_runtime.h>
#include <cuda_fp16.h>
#include <cstdint>

// ---------------- problem constants ----------------
#define BB    8
#define TT    2048
#define CCH   1024
#define BT    (BB*TT)          // 16384 rows
#define N3    (3*CCH)          // 3072
#define N4    (4*CCH)          // 4096

// ---------------- scratch (device globals, no allocation) ----------------
__device__ __half g_ln1h[(size_t)BT*CCH];
__device__ float  g_K  [(size_t)BT*CCH];
__device__ float  g_V  [(size_t)BT*CCH];
__device__ float  g_R  [(size_t)BT*CCH];
__device__ float  g_X1 [(size_t)BT*CCH];
__device__ float  g_XN [(size_t)BT*CCH];
__device__ __half g_XNh[(size_t)BT*CCH];
__device__ __half g_Hh [(size_t)BT*N4];
__device__ __half g_Wtm[(size_t)CCH*N3];   // transposed: (3C, C) half
__device__ __half g_Wcm[(size_t)CCH*N4];   // transposed: (4C, C) half
__device__ __half g_Wcp[(size_t)N4*CCH];   // transposed: (C, 4C) half

// ---------------- helpers ----------------
__device__ __forceinline__ float sigmoidf_(float z) {
    return 1.0f / (1.0f + __expf(-z));
}
__device__ __forceinline__ void cp16s(uint32_t dst, const void* src) {
    asm volatile("cp.async.cg.shared.global [%0], [%1], 16;\n"
                 :: "r"(dst), "l"(src) : "memory");
}
#define CP_COMMIT() asm volatile("cp.async.commit_group;\n" ::: "memory")
#define CP_WAIT(Ng) asm volatile("cp.async.wait_group %0;\n" :: "n"(Ng) : "memory")

__device__ __forceinline__ void mma_f16(float* c, const uint32_t* a, const uint32_t* b) {
    asm volatile(
        "mma.sync.aligned.m16n8k16.row.col.f32.f16.f16.f32 "
        "{%0,%1,%2,%3}, {%4,%5,%6,%7}, {%8,%9}, {%0,%1,%2,%3};"
        : "+f"(c[0]), "+f"(c[1]), "+f"(c[2]), "+f"(c[3])
        : "r"(a[0]), "r"(a[1]), "r"(a[2]), "r"(a[3]), "r"(b[0]), "r"(b[1]));
}
__device__ __forceinline__ void ldsm4(uint32_t& r0, uint32_t& r1,
                                      uint32_t& r2, uint32_t& r3, uint32_t a) {
    asm volatile("ldmatrix.sync.aligned.m8n8.x4.shared.b16 {%0,%1,%2,%3}, [%4];"
                 : "=r"(r0), "=r"(r1), "=r"(r2), "=r"(r3) : "r"(a));
}

// ---------------- transpose + fp16 convert (W K x N -> Wt N x K) ----------
__global__ void __launch_bounds__(256) transpose_h(const float* __restrict__ in,
                                                   __half* __restrict__ out,
                                                   int Kd, int Nd)
{
    __shared__ float tile[32][33];
    const int bx = blockIdx.x * 32;   // N
    const int by = blockIdx.y * 32;   // K
    const int tx = threadIdx.x, ty = threadIdx.y;
    #pragma unroll
    for (int i = 0; i < 32; i += 8)
        tile[ty + i][tx] = in[(size_t)(by + ty + i) * Nd + bx + tx];
    __syncthreads();
    #pragma unroll
    for (int i = 0; i < 32; i += 8)
        out[(size_t)(bx + ty + i) * Kd + by + tx] = __float2half_rn(tile[tx][ty + i]);
}

// ---------------- LayerNorm: half output (+ optional fp32 copy) -----------
__global__ void __launch_bounds__(256) ln_kernel(const float* __restrict__ x,
                                                 const float* __restrict__ g,
                                                 const float* __restrict__ b,
                                                 __half* __restrict__ outh,
                                                 float* __restrict__ outf)
{
    const int row  = blockIdx.x;
    const int tid  = threadIdx.x;
    const int lane = tid & 31, wid = tid >> 5;

    const float4* xr = (const float4*)(x + (size_t)row * CCH);
    float4 v = xr[tid];
    float s = v.x + v.y + v.z + v.w;
    float q = v.x*v.x + v.y*v.y + v.z*v.z + v.w*v.w;

    #pragma unroll
    for (int o = 16; o > 0; o >>= 1) {
        s += __shfl_xor_sync(0xffffffffu, s, o);
        q += __shfl_xor_sync(0xffffffffu, q, o);
    }
    __shared__ float sh_s[8], sh_q[8];
    if (lane == 0) { sh_s[wid] = s; sh_q[wid] = q; }
    __syncthreads();
    float S = 0.f, Q = 0.f;
    #pragma unroll
    for (int i = 0; i < 8; i++) { S += sh_s[i]; Q += sh_q[i]; }

    const float mean = S * (1.0f / CCH);
    float var = Q * (1.0f / CCH) - mean * mean;
    var = fmaxf(var, 0.0f);
    const float rstd = rsqrtf(var + 1e-5f);

    float4 gg = ((const float4*)g)[tid];
    float4 bb4 = ((const float4*)b)[tid];
    float4 o4;
    o4.x = (v.x - mean) * rstd * gg.x + bb4.x;
    o4.y = (v.y - mean) * rstd * gg.y + bb4.y;
    o4.z = (v.z - mean) * rstd * gg.z + bb4.z;
    o4.w = (v.w - mean) * rstd * gg.w + bb4.w;

    __half2 h0 = __floats2half2_rn(o4.x, o4.y);
    __half2 h1 = __floats2half2_rn(o4.z, o4.w);
    uint2 hh; hh.x = *(uint32_t*)&h0; hh.y = *(uint32_t*)&h1;
    ((uint2*)(outh + (size_t)row * CCH))[tid] = hh;
    if (outf) ((float4*)(outf + (size_t)row * CCH))[tid] = o4;
}

// ---------------- WKV scan: EXACT reference recurrence ----------------
// Same math as the R12-passing version (reference recurrence in scaled
// parameterization, renorm every 8 steps), with a DEPTH-8 register
// pipeline: step t+8's operands are loaded while step t computes, putting
// up to 32 loads in flight to cover DRAM latency (was depth 1).
__global__ void __launch_bounds__(32) wkv_kernel(const float* __restrict__ td,
                                                 const float* __restrict__ tf,
                                                 const float* __restrict__ Kb,
                                                 const float* __restrict__ Vb,
                                                 const float* __restrict__ Rb,
                                                 const float* __restrict__ x,
                                                 float* __restrict__ X1,
                                                 float* __restrict__ state)
{
    const int bidx = blockIdx.x >> 5;
    const int c    = ((blockIdx.x & 31) << 5) + threadIdx.x;
    const float w = td[c], u = tf[c];
    const float E   = __expf(w);
    const float Eu  = __expf(u);
    const float eps = 1e-8f;

    const size_t base = (size_t)bidx * TT * CCH + c;

    float kb[8], vb[8], rb[8], xb[8];
    #pragma unroll
    for (int j = 0; j < 8; ++j) {
        const size_t i0 = base + (size_t)j * CCH;
        kb[j] = Kb[i0]; vb[j] = Vb[i0]; rb[j] = Rb[i0]; xb[j] = x[i0];
    }

    float sigma = kb[0];       // so ek(t=0) = 1 (matches bb after step 0)
    float aa = 0.0f, bt = 0.0f;
    size_t idx = base;

    for (int t0 = 0; t0 < TT; t0 += 8) {
        #pragma unroll
        for (int j = 0; j < 8; ++j) {
            const float kk = kb[j], vv = vb[j], rr = rb[j], xx = xb[j];
            // prefetch step t0+j+8 into this slot (issued early, consumed
            // 8 iterations later)
            if (t0 + j + 8 < TT) {
                const size_t ip = idx + (size_t)(8 * CCH);
                kb[j] = Kb[ip]; vb[j] = Vb[ip]; rb[j] = Rb[ip]; xb[j] = x[ip];
            }
            const float ek  = __expf(kk - sigma);   // off the carried chain
            const float eku = Eu * ek;
            // ---- output (exact scaled form of reference y-step) ----
            const float mp = fmaxf(bt, eku);
            const float y  = fmaf(bt, aa, eku * vv) / fmaf(eps, mp, bt + eku);
            X1[idx] = xx + rr * y;
            // ---- state update (exact scaled form) ----
            const float Ebt = E * bt;
            const float m   = fmaxf(Ebt, ek);
            aa = fmaf(Ebt, aa, ek * vv) / m;
            bt = fmaf(eps, m, Ebt + ek);
            idx += CCH;
        }
        sigma += __logf(bt);    // renormalize window (t & 7) == 7
        bt = 1.0f;
    }
    state[((size_t)bidx * CCH + c) * 2 + 0] = aa;
    state[((size_t)bidx * CCH + c) * 2 + 1] = sigma;   // + log(1)
}

// ---------------- FP16 mma.sync GEMM with fused epilogues ---------------
// C = A(MxK, row, half) @ Wt(NxK, row, half)^T ; fp32 accumulate.
// CTA: 128(M) x BN(N), BK=32, 256 thr, 8 warps (2x4), warp tile 64 x BN/4.
// BN templated (256 or 128) to kill wave quantization per GEMM shape.
#define GBK    32
#define ROWB   80                      // bytes per smem row (40 halves)
#define STGA   (128*ROWB)              // 10240 B
#define NSTG   4

#define LOADSTAGE(s_, kt_) do {                                               \
    uint32_t ab_ = smem + (uint32_t)(s_) * STG_;                              \
    uint32_t bb_ = ab_ + STGA;                                                \
    _Pragma("unroll")                                                         \
    for (int i_ = 0; i_ < 2; i_++) {                                          \
        int idx_ = tid + i_*256; int r_ = idx_ >> 2; int c_ = idx_ & 3;       \
        cp16s(ab_ + r_*ROWB + c_*16, A + (size_t)(bm+r_)*K + (kt_)*GBK + c_*8); \
    }                                                                         \
    _Pragma("unroll")                                                         \
    for (int i_ = 0; i_ < BN/64; i_++) {                                      \
        int idx_ = tid + i_*256; int r_ = idx_ >> 2; int c_ = idx_ & 3;       \
        cp16s(bb_ + r_*ROWB + c_*16, Wt + (size_t)(bn+r_)*K + (kt_)*GBK + c_*8); \
    }                                                                         \
} while (0)

#define COMPUTE(st_) do {                                                     \
    const uint32_t aB_ = smem + (st_)*STG_ + (uint32_t)(wm)*ROWB + aLane;     \
    const uint32_t bB_ = smem + (st_)*STG_ + STGA + (uint32_t)(wn)*ROWB + bLane; \
    _Pragma("unroll")                                                         \
    for (int ks = 0; ks < 2; ++ks) {                                          \
        uint32_t af[4][4]; uint32_t bf[NT][2];                                \
        _Pragma("unroll")                                                     \
        for (int mt = 0; mt < 4; ++mt)                                        \
            ldsm4(af[mt][0], af[mt][1], af[mt][2], af[mt][3],                 \
                  aB_ + mt*16*ROWB + ks*32);                                  \
        _Pragma("unroll")                                                     \
        for (int np = 0; np < NT/2; ++np)                                     \
            ldsm4(bf[2*np][0], bf[2*np][1], bf[2*np+1][0], bf[2*np+1][1],     \
                  bB_ + np*16*ROWB + ks*32);                                  \
        _Pragma("unroll")                                                     \
        for (int mt = 0; mt < 4; ++mt)                                        \
            _Pragma("unroll")                                                 \
            for (int nt = 0; nt < NT; ++nt)                                   \
                mma_f16(acc[mt][nt], af[mt], bf[nt]);                         \
    }                                                                         \
} while (0)

template<int EPI, int BN>
__global__ void __launch_bounds__(256) gemm_f16_kernel(
    const __half* __restrict__ A, const __half* __restrict__ Wt,
    int K, int N,
    const float* __restrict__ px,   // EPI0: x ; EPI1/2: X1
    const float* __restrict__ pxn,  // EPI2: XN (fp32)
    const float* __restrict__ m0,   // tmk / cmk / cmr
    const float* __restrict__ m1,   // tmv
    const float* __restrict__ m2,   // tmr
    float* __restrict__ o0, float* __restrict__ o1, float* __restrict__ o2)
{
    extern __shared__ char dsm[];

    constexpr int BNW  = BN / 4;        // n extent per warp
    constexpr int NT   = BNW / 8;       // n-tiles (8 wide) per warp
    constexpr int STG_ = STGA + BN*ROWB;

    const int tid  = threadIdx.x;
    const int lane = tid & 31;
    const int w    = tid >> 5;
    const int gq   = lane >> 2;
    const int t4   = lane & 3;
    const int wm   = (w & 1) * 64;
    const int wn   = (w >> 1) * BNW;
    const int bm   = blockIdx.y * 128;
    const int bn   = blockIdx.x * BN;
    const uint32_t smem = (uint32_t)__cvta_generic_to_shared(dsm);

    // ldmatrix lane address components
    const uint32_t aLane = (uint32_t)(lane & 15) * ROWB + (uint32_t)(lane >> 4) * 16;
    const uint32_t bLane = ((uint32_t)(lane & 7) + (uint32_t)(lane >> 4) * 8) * ROWB
                         + (uint32_t)((lane >> 3) & 1) * 16;

    float acc[4][NT][4];
    #pragma unroll
    for (int i = 0; i < 4; i++)
        #pragma unroll
        for (int j = 0; j < NT; j++)
            #pragma unroll
            for (int q = 0; q < 4; q++) acc[i][j][q] = 0.0f;

    const int ntk = K / GBK;
    LOADSTAGE(0, 0); CP_COMMIT();
    LOADSTAGE(1, 1); CP_COMMIT();
    LOADSTAGE(2, 2); CP_COMMIT();

    for (int kt = 0; kt < ntk; ++kt) {
        CP_WAIT(2);
        __syncthreads();
        const int lt = kt + 3;
        if (lt < ntk) {
            LOADSTAGE(lt & 3, lt);
        }
        CP_COMMIT();
        COMPUTE(kt & 3);
    }

#undef LOADSTAGE
#undef COMPUTE

    // ---------------- fused epilogue ----------------
    #pragma unroll
    for (int mt = 0; mt < 4; ++mt) {
        #pragma unroll
        for (int h = 0; h < 2; ++h) {
            const int m = bm + wm + mt*16 + gq + h*8;
            const int t = m & (TT - 1);
            int pm;
            if (EPI == 0) pm = (t == 0) ? m : (m - 1);              // repeat first
            else          pm = (t == 0) ? (m + (TT - 1)) : (m - 1); // wrap last->front
            #pragma unroll
            for (int nt2 = 0; nt2 < NT; ++nt2) {
                const int n = bn + wn + nt2*8 + t4*2;
                const float v0 = acc[mt][nt2][h*2];
                const float v1 = acc[mt][nt2][h*2 + 1];
                if (EPI == 0) {
                    const int sec = n >> 10;
                    const int cc  = n & (CCH - 1);
                    const float xp0 = px[(size_t)pm*CCH + cc];
                    const float xp1 = px[(size_t)pm*CCH + cc + 1];
                    float* dst; const float* mk;
                    if (sec == 0)      { dst = o0; mk = m0; }
                    else if (sec == 1) { dst = o1; mk = m1; }
                    else               { dst = o2; mk = m2; }
                    const float mk0 = mk[cc], mk1 = mk[cc + 1];
                    float r0 = v0 * mk0 + xp0 * (1.0f - mk0);
                    float r1 = v1 * mk1 + xp1 * (1.0f - mk1);
                    if (sec == 2) { r0 = sigmoidf_(r0); r1 = sigmoidf_(r1); }
                    *(float2*)&dst[(size_t)m*CCH + cc] = make_float2(r0, r1);
                } else if (EPI == 1) {
                    const int cc = n & (CCH - 1);
                    const float xp0 = px[(size_t)pm*CCH + cc];
                    const float xp1 = px[(size_t)pm*CCH + cc + 1];
                    const float mk0 = m0[cc], mk1 = m0[cc + 1];
                    float k0 = fmaxf(v0 * mk0 + xp0 * (1.0f - mk0), 0.0f);
                    float k1 = fmaxf(v1 * mk1 + xp1 * (1.0f - mk1), 0.0f);
                    __half2 hv = __floats2half2_rn(k0 * k0, k1 * k1);
                    *(__half2*)&((__half*)o0)[(size_t)m*N + n] = hv;
                } else {
                    const float xp0 = px [(size_t)pm*CCH + n];
                    const float xp1 = px [(size_t)pm*CCH + n + 1];
                    const float xn0 = pxn[(size_t)m *CCH + n];
                    const float xn1 = pxn[(size_t)m *CCH + n + 1];
                    const float mk0 = m0[n], mk1 = m0[n + 1];
                    const float rr0 = sigmoidf_(xn0 * mk0 + xp0 * (1.0f - mk0));
                    const float rr1 = sigmoidf_(xn1 * mk1 + xp1 * (1.0f - mk1));
                    const float x0  = px[(size_t)m*CCH + n];
                    const float x1v = px[(size_t)m*CCH + n + 1];
                    *(float2*)&o0[(size_t)m*CCH + n] =
                        make_float2(x0 + rr0 * v0, x1v + rr1 * v1);
                }
            }
        }
    }
}

// ---------------- launcher ----------------
#define SMEM_OF(BN) (NSTG * (STGA + (BN)*ROWB))

extern "C" void kernel_launch(void* const* d_in, const int* in_sizes, int n_in,
                              void* d_out, int out_size)
{
    const float* x    = (const float*)d_in[0];
    const float* td   = (const float*)d_in[1];
    const float* tfst = (const float*)d_in[2];
    const float* W_tm = (const float*)d_in[3];
    const float* g1   = (const float*)d_in[4];
    const float* b1   = (const float*)d_in[5];
    const float* tmk  = (const float*)d_in[6];
    const float* tmv  = (const float*)d_in[7];
    const float* tmr  = (const float*)d_in[8];
    const float* W_cm = (const float*)d_in[9];
    const float* W_cp = (const float*)d_in[10];
    const float* g2   = (const float*)d_in[11];
    const float* b2   = (const float*)d_in[12];
    const float* cmk  = (const float*)d_in[13];
    const float* cmr  = (const float*)d_in[14];
    float* out = (float*)d_out;

    __half *ln1h, *XNh, *Hh, *Wtm, *Wcm, *Wcp;
    float *Kb, *Vb, *Rb, *X1, *XN;
    cudaGetSymbolAddress((void**)&ln1h, g_ln1h);
    cudaGetSymbolAddress((void**)&Kb,  g_K);
    cudaGetSymbolAddress((void**)&Vb,  g_V);
    cudaGetSymbolAddress((void**)&Rb,  g_R);
    cudaGetSymbolAddress((void**)&X1,  g_X1);
    cudaGetSymbolAddress((void**)&XN,  g_XN);
    cudaGetSymbolAddress((void**)&XNh, g_XNh);
    cudaGetSymbolAddress((void**)&Hh,  g_Hh);
    cudaGetSymbolAddress((void**)&Wtm, g_Wtm);
    cudaGetSymbolAddress((void**)&Wcm, g_Wcm);
    cudaGetSymbolAddress((void**)&Wcp, g_Wcp);

    static bool attr_done = false;
    if (!attr_done) {
        cudaFuncSetAttribute(gemm_f16_kernel<0,128>,
            cudaFuncAttributeMaxDynamicSharedMemorySize, SMEM_OF(128));
        cudaFuncSetAttribute(gemm_f16_kernel<1,256>,
            cudaFuncAttributeMaxDynamicSharedMemorySize, SMEM_OF(256));
        cudaFuncSetAttribute(gemm_f16_kernel<2,128>,
            cudaFuncAttributeMaxDynamicSharedMemorySize, SMEM_OF(128));
        attr_done = true;
    }

    // 0) transpose + fp16-convert weights: W(K,N) -> Wt(N,K)
    transpose_h<<<dim3(N3/32,  CCH/32), dim3(32,8)>>>(W_tm, Wtm, CCH, N3);
    transpose_h<<<dim3(N4/32,  CCH/32), dim3(32,8)>>>(W_cm, Wcm, CCH, N4);
    transpose_h<<<dim3(CCH/32, N4/32),  dim3(32,8)>>>(W_cp, Wcp, N4, CCH);

    // 1) LN1 -> half
    ln_kernel<<<BT, 256>>>(x, g1, b1, ln1h, nullptr);

    // 2) GEMM1 (16384x1024x3072) + time-mix epilogue -> K,V,R (fp32)
    gemm_f16_kernel<0,128><<<dim3(N3/128, BT/128), 256, SMEM_OF(128)>>>(
        ln1h, Wtm, CCH, N3, x, nullptr, tmk, tmv, tmr, Kb, Vb, Rb);

    // 3) WKV scan + residual -> X1, new_state into d_out tail
    wkv_kernel<<<BB * (CCH/32), 32>>>(td, tfst, Kb, Vb, Rb, x, X1,
                                      out + (size_t)BT * CCH);

    // 4) LN2 -> half (GEMM input) + fp32 (final epilogue)
    ln_kernel<<<BT, 256>>>(X1, g2, b2, XNh, XN);

    // 5) GEMM2 (16384x1024x4096) + channel-mix + relu^2 -> H (half)
    gemm_f16_kernel<1,256><<<dim3(N4/256, BT/128), 256, SMEM_OF(256)>>>(
        XNh, Wcm, CCH, N4, X1, nullptr, cmk, nullptr, nullptr,
        (float*)Hh, nullptr, nullptr);

    // 6) GEMM3 (16384x4096x1024) + final residual -> d_out
    gemm_f16_kernel<2,128><<<dim3(CCH/128, BT/128), 256, SMEM_OF(128)>>>(
        Hh, Wcp, N4, CCH, X1, XN, cmr, nullptr, nullptr,
        out, nullptr, nullptr);
}

// round 14
// speedup vs baseline: 5.6750x; 1.0628x over previous
#include <cuda_runtime.h>
#include <cuda_fp16.h>
#include <cstdint>

// ---------------- problem constants ----------------
#define BB    8
#define TT    2048
#define CCH   1024
#define BT    (BB*TT)          // 16384 rows
#define N3    (3*CCH)          // 3072
#define N4    (4*CCH)          // 4096

// ---------------- scratch (device globals, no allocation) ----------------
__device__ __half g_ln1h[(size_t)BT*CCH];
__device__ float  g_K  [(size_t)BT*CCH];
__device__ float  g_V  [(size_t)BT*CCH];
__device__ float  g_R  [(size_t)BT*CCH];
__device__ float  g_X1 [(size_t)BT*CCH];
__device__ float  g_XN [(size_t)BT*CCH];
__device__ __half g_XNh[(size_t)BT*CCH];
__device__ __half g_Hh [(size_t)BT*N4];
__device__ __half g_Wtm[(size_t)CCH*N3];   // transposed: (3C, C) half
__device__ __half g_Wcm[(size_t)CCH*N4];   // transposed: (4C, C) half
__device__ __half g_Wcp[(size_t)N4*CCH];   // transposed: (C, 4C) half

// ---------------- helpers ----------------
__device__ __forceinline__ float sigmoidf_(float z) {
    return 1.0f / (1.0f + __expf(-z));
}
__device__ __forceinline__ void cp16s(uint32_t dst, const void* src) {
    asm volatile("cp.async.cg.shared.global [%0], [%1], 16;\n"
                 :: "r"(dst), "l"(src) : "memory");
}
#define CP_COMMIT() asm volatile("cp.async.commit_group;\n" ::: "memory")
#define CP_WAIT(Ng) asm volatile("cp.async.wait_group %0;\n" :: "n"(Ng) : "memory")

__device__ __forceinline__ void mma_f16(float* c, const uint32_t* a, const uint32_t* b) {
    asm volatile(
        "mma.sync.aligned.m16n8k16.row.col.f32.f16.f16.f32 "
        "{%0,%1,%2,%3}, {%4,%5,%6,%7}, {%8,%9}, {%0,%1,%2,%3};"
        : "+f"(c[0]), "+f"(c[1]), "+f"(c[2]), "+f"(c[3])
        : "r"(a[0]), "r"(a[1]), "r"(a[2]), "r"(a[3]), "r"(b[0]), "r"(b[1]));
}
__device__ __forceinline__ void ldsm4(uint32_t& r0, uint32_t& r1,
                                      uint32_t& r2, uint32_t& r3, uint32_t a) {
    asm volatile("ldmatrix.sync.aligned.m8n8.x4.shared.b16 {%0,%1,%2,%3}, [%4];"
                 : "=r"(r0), "=r"(r1), "=r"(r2), "=r"(r3) : "r"(a));
}

// ---------------- transpose + fp16 convert (W K x N -> Wt N x K) ----------
__global__ void __launch_bounds__(256) transpose_h(const float* __restrict__ in,
                                                   __half* __restrict__ out,
                                                   int Kd, int Nd)
{
    __shared__ float tile[32][33];
    const int bx = blockIdx.x * 32;   // N
    const int by = blockIdx.y * 32;   // K
    const int tx = threadIdx.x, ty = threadIdx.y;
    #pragma unroll
    for (int i = 0; i < 32; i += 8)
        tile[ty + i][tx] = in[(size_t)(by + ty + i) * Nd + bx + tx];
    __syncthreads();
    #pragma unroll
    for (int i = 0; i < 32; i += 8)
        out[(size_t)(bx + ty + i) * Kd + by + tx] = __float2half_rn(tile[tx][ty + i]);
}

// ---------------- LayerNorm: half output (+ optional fp32 copy) -----------
__global__ void __launch_bounds__(256) ln_kernel(const float* __restrict__ x,
                                                 const float* __restrict__ g,
                                                 const float* __restrict__ b,
                                                 __half* __restrict__ outh,
                                                 float* __restrict__ outf)
{
    const int row  = blockIdx.x;
    const int tid  = threadIdx.x;
    const int lane = tid & 31, wid = tid >> 5;

    const float4* xr = (const float4*)(x + (size_t)row * CCH);
    float4 v = xr[tid];
    float s = v.x + v.y + v.z + v.w;
    float q = v.x*v.x + v.y*v.y + v.z*v.z + v.w*v.w;

    #pragma unroll
    for (int o = 16; o > 0; o >>= 1) {
        s += __shfl_xor_sync(0xffffffffu, s, o);
        q += __shfl_xor_sync(0xffffffffu, q, o);
    }
    __shared__ float sh_s[8], sh_q[8];
    if (lane == 0) { sh_s[wid] = s; sh_q[wid] = q; }
    __syncthreads();
    float S = 0.f, Q = 0.f;
    #pragma unroll
    for (int i = 0; i < 8; i++) { S += sh_s[i]; Q += sh_q[i]; }

    const float mean = S * (1.0f / CCH);
    float var = Q * (1.0f / CCH) - mean * mean;
    var = fmaxf(var, 0.0f);
    const float rstd = rsqrtf(var + 1e-5f);

    float4 gg = ((const float4*)g)[tid];
    float4 bb4 = ((const float4*)b)[tid];
    float4 o4;
    o4.x = (v.x - mean) * rstd * gg.x + bb4.x;
    o4.y = (v.y - mean) * rstd * gg.y + bb4.y;
    o4.z = (v.z - mean) * rstd * gg.z + bb4.z;
    o4.w = (v.w - mean) * rstd * gg.w + bb4.w;

    __half2 h0 = __floats2half2_rn(o4.x, o4.y);
    __half2 h1 = __floats2half2_rn(o4.z, o4.w);
    uint2 hh; hh.x = *(uint32_t*)&h0; hh.y = *(uint32_t*)&h1;
    ((uint2*)(outh + (size_t)row * CCH))[tid] = hh;
    if (outf) ((float4*)(outf + (size_t)row * CCH))[tid] = o4;
}

// ---------------- WKV scan: EXACT reference recurrence ----------------
// Reference recurrence in scaled parameterization (renorm every 8 steps),
// depth-8 register pipeline: step t+8's operands load while step t computes.
__global__ void __launch_bounds__(32) wkv_kernel(const float* __restrict__ td,
                                                 const float* __restrict__ tf,
                                                 const float* __restrict__ Kb,
                                                 const float* __restrict__ Vb,
                                                 const float* __restrict__ Rb,
                                                 const float* __restrict__ x,
                                                 float* __restrict__ X1,
                                                 float* __restrict__ state)
{
    const int bidx = blockIdx.x >> 5;
    const int c    = ((blockIdx.x & 31) << 5) + threadIdx.x;
    const float w = td[c], u = tf[c];
    const float E   = __expf(w);
    const float Eu  = __expf(u);
    const float eps = 1e-8f;

    const size_t base = (size_t)bidx * TT * CCH + c;

    float kb[8], vb[8], rb[8], xb[8];
    #pragma unroll
    for (int j = 0; j < 8; ++j) {
        const size_t i0 = base + (size_t)j * CCH;
        kb[j] = Kb[i0]; vb[j] = Vb[i0]; rb[j] = Rb[i0]; xb[j] = x[i0];
    }

    float sigma = kb[0];       // so ek(t=0) = 1 (matches bb after step 0)
    float aa = 0.0f, bt = 0.0f;
    size_t idx = base;

    for (int t0 = 0; t0 < TT; t0 += 8) {
        #pragma unroll
        for (int j = 0; j < 8; ++j) {
            const float kk = kb[j], vv = vb[j], rr = rb[j], xx = xb[j];
            if (t0 + j + 8 < TT) {
                const size_t ip = idx + (size_t)(8 * CCH);
                kb[j] = Kb[ip]; vb[j] = Vb[ip]; rb[j] = Rb[ip]; xb[j] = x[ip];
            }
            const float ek  = __expf(kk - sigma);   // off the carried chain
            const float eku = Eu * ek;
            const float mp = fmaxf(bt, eku);
            const float y  = fmaf(bt, aa, eku * vv) / fmaf(eps, mp, bt + eku);
            X1[idx] = xx + rr * y;
            const float Ebt = E * bt;
            const float m   = fmaxf(Ebt, ek);
            aa = fmaf(Ebt, aa, ek * vv) / m;
            bt = fmaf(eps, m, Ebt + ek);
            idx += CCH;
        }
        sigma += __logf(bt);    // renormalize window (t & 7) == 7
        bt = 1.0f;
    }
    state[((size_t)bidx * CCH + c) * 2 + 0] = aa;
    state[((size_t)bidx * CCH + c) * 2 + 1] = sigma;   // + log(1)
}

// ---------------- FP16 mma.sync GEMM with fused epilogues ---------------
// C = A(MxK, row, half) @ Wt(NxK, row, half)^T ; fp32 accumulate.
// CTA: 128(M) x 128(N), BK=32, 256 thr, 8 warps (2x4), warp tile 64x32.
// 4-stage cp.async, one sync/k-tile. __launch_bounds__(256,2): regs<=128,
// smem 80KB -> TWO CTAs per SM so sync/prologue/epilogue bubbles overlap.
#define GBK    32
#define ROWB   80                      // bytes per smem row (40 halves)
#define STGA   (128*ROWB)              // 10240 B
#define NSTG   4
#define BN     128
#define STG_   (STGA + BN*ROWB)        // 20480 B
#define SMEM_TOT (NSTG*STG_)           // 81920 B

#define LOADSTAGE(s_, kt_) do {                                               \
    uint32_t ab_ = smem + (uint32_t)(s_) * STG_;                              \
    uint32_t bb_ = ab_ + STGA;                                                \
    _Pragma("unroll")                                                         \
    for (int i_ = 0; i_ < 2; i_++) {                                          \
        int idx_ = tid + i_*256; int r_ = idx_ >> 2; int c_ = idx_ & 3;       \
        cp16s(ab_ + r_*ROWB + c_*16, A + (size_t)(bm+r_)*K + (kt_)*GBK + c_*8); \
    }                                                                         \
    _Pragma("unroll")                                                         \
    for (int i_ = 0; i_ < 2; i_++) {                                          \
        int idx_ = tid + i_*256; int r_ = idx_ >> 2; int c_ = idx_ & 3;       \
        cp16s(bb_ + r_*ROWB + c_*16, Wt + (size_t)(bn+r_)*K + (kt_)*GBK + c_*8); \
    }                                                                         \
} while (0)

#define COMPUTE(st_) do {                                                     \
    const uint32_t aB_ = smem + (st_)*STG_ + (uint32_t)(wm)*ROWB + aLane;     \
    const uint32_t bB_ = smem + (st_)*STG_ + STGA + (uint32_t)(wn)*ROWB + bLane; \
    _Pragma("unroll")                                                         \
    for (int ks = 0; ks < 2; ++ks) {                                          \
        uint32_t af[4][4]; uint32_t bf[4][2];                                 \
        _Pragma("unroll")                                                     \
        for (int mt = 0; mt < 4; ++mt)                                        \
            ldsm4(af[mt][0], af[mt][1], af[mt][2], af[mt][3],                 \
                  aB_ + mt*16*ROWB + ks*32);                                  \
        _Pragma("unroll")                                                     \
        for (int np = 0; np < 2; ++np)                                        \
            ldsm4(bf[2*np][0], bf[2*np][1], bf[2*np+1][0], bf[2*np+1][1],     \
                  bB_ + np*16*ROWB + ks*32);                                  \
        _Pragma("unroll")                                                     \
        for (int mt = 0; mt < 4; ++mt)                                        \
            _Pragma("unroll")                                                 \
            for (int nt = 0; nt < 4; ++nt)                                    \
                mma_f16(acc[mt][nt], af[mt], bf[nt]);                         \
    }                                                                         \
} while (0)

template<int EPI>
__global__ void __launch_bounds__(256, 2) gemm_f16_kernel(
    const __half* __restrict__ A, const __half* __restrict__ Wt,
    int K, int N,
    const float* __restrict__ px,   // EPI0: x ; EPI1/2: X1
    const float* __restrict__ pxn,  // EPI2: XN (fp32)
    const float* __restrict__ m0,   // tmk / cmk / cmr
    const float* __restrict__ m1,   // tmv
    const float* __restrict__ m2,   // tmr
    float* __restrict__ o0, float* __restrict__ o1, float* __restrict__ o2)
{
    extern __shared__ char dsm[];

    const int tid  = threadIdx.x;
    const int lane = tid & 31;
    const int w    = tid >> 5;
    const int gq   = lane >> 2;
    const int t4   = lane & 3;
    const int wm   = (w & 1) * 64;      // 2x4 warp grid: 64(M) x 32(N) tiles
    const int wn   = (w >> 1) * 32;
    const int bm   = blockIdx.y * 128;
    const int bn   = blockIdx.x * BN;
    const uint32_t smem = (uint32_t)__cvta_generic_to_shared(dsm);

    // ldmatrix lane address components
    const uint32_t aLane = (uint32_t)(lane & 15) * ROWB + (uint32_t)(lane >> 4) * 16;
    const uint32_t bLane = ((uint32_t)(lane & 7) + (uint32_t)(lane >> 4) * 8) * ROWB
                         + (uint32_t)((lane >> 3) & 1) * 16;

    float acc[4][4][4];
    #pragma unroll
    for (int i = 0; i < 4; i++)
        #pragma unroll
        for (int j = 0; j < 4; j++)
            #pragma unroll
            for (int q = 0; q < 4; q++) acc[i][j][q] = 0.0f;

    const int ntk = K / GBK;
    LOADSTAGE(0, 0); CP_COMMIT();
    LOADSTAGE(1, 1); CP_COMMIT();
    LOADSTAGE(2, 2); CP_COMMIT();

    for (int kt = 0; kt < ntk; ++kt) {
        CP_WAIT(2);
        __syncthreads();
        const int lt = kt + 3;
        if (lt < ntk) {
            LOADSTAGE(lt & 3, lt);
        }
        CP_COMMIT();
        COMPUTE(kt & 3);
    }

#undef LOADSTAGE
#undef COMPUTE

    // ---------------- fused epilogue ----------------
    #pragma unroll
    for (int mt = 0; mt < 4; ++mt) {
        #pragma unroll
        for (int h = 0; h < 2; ++h) {
            const int m = bm + wm + mt*16 + gq + h*8;
            const int t = m & (TT - 1);
            int pm;
            if (EPI == 0) pm = (t == 0) ? m : (m - 1);              // repeat first
            else          pm = (t == 0) ? (m + (TT - 1)) : (m - 1); // wrap last->front
            #pragma unroll
            for (int nt2 = 0; nt2 < 4; ++nt2) {
                const int n = bn + wn + nt2*8 + t4*2;
                const float v0 = acc[mt][nt2][h*2];
                const float v1 = acc[mt][nt2][h*2 + 1];
                if (EPI == 0) {
                    const int sec = n >> 10;
                    const int cc  = n & (CCH - 1);
                    const float xp0 = px[(size_t)pm*CCH + cc];
                    const float xp1 = px[(size_t)pm*CCH + cc + 1];
                    float* dst; const float* mk;
                    if (sec == 0)      { dst = o0; mk = m0; }
                    else if (sec == 1) { dst = o1; mk = m1; }
                    else               { dst = o2; mk = m2; }
                    const float mk0 = mk[cc], mk1 = mk[cc + 1];
                    float r0 = v0 * mk0 + xp0 * (1.0f - mk0);
                    float r1 = v1 * mk1 + xp1 * (1.0f - mk1);
                    if (sec == 2) { r0 = sigmoidf_(r0); r1 = sigmoidf_(r1); }
                    *(float2*)&dst[(size_t)m*CCH + cc] = make_float2(r0, r1);
                } else if (EPI == 1) {
                    const int cc = n & (CCH - 1);
                    const float xp0 = px[(size_t)pm*CCH + cc];
                    const float xp1 = px[(size_t)pm*CCH + cc + 1];
                    const float mk0 = m0[cc], mk1 = m0[cc + 1];
                    float k0 = fmaxf(v0 * mk0 + xp0 * (1.0f - mk0), 0.0f);
                    float k1 = fmaxf(v1 * mk1 + xp1 * (1.0f - mk1), 0.0f);
                    __half2 hv = __floats2half2_rn(k0 * k0, k1 * k1);
                    *(__half2*)&((__half*)o0)[(size_t)m*N + n] = hv;
                } else {
                    const float xp0 = px [(size_t)pm*CCH + n];
                    const float xp1 = px [(size_t)pm*CCH + n + 1];
                    const float xn0 = pxn[(size_t)m *CCH + n];
                    const float xn1 = pxn[(size_t)m *CCH + n + 1];
                    const float mk0 = m0[n], mk1 = m0[n + 1];
                    const float rr0 = sigmoidf_(xn0 * mk0 + xp0 * (1.0f - mk0));
                    const float rr1 = sigmoidf_(xn1 * mk1 + xp1 * (1.0f - mk1));
                    const float x0  = px[(size_t)m*CCH + n];
                    const float x1v = px[(size_t)m*CCH + n + 1];
                    *(float2*)&o0[(size_t)m*CCH + n] =
                        make_float2(x0 + rr0 * v0, x1v + rr1 * v1);
                }
            }
        }
    }
}

// ---------------- launcher ----------------
extern "C" void kernel_launch(void* const* d_in, const int* in_sizes, int n_in,
                              void* d_out, int out_size)
{
    const float* x    = (const float*)d_in[0];
    const float* td   = (const float*)d_in[1];
    const float* tfst = (const float*)d_in[2];
    const float* W_tm = (const float*)d_in[3];
    const float* g1   = (const float*)d_in[4];
    const float* b1   = (const float*)d_in[5];
    const float* tmk  = (const float*)d_in[6];
    const float* tmv  = (const float*)d_in[7];
    const float* tmr  = (const float*)d_in[8];
    const float* W_cm = (const float*)d_in[9];
    const float* W_cp = (const float*)d_in[10];
    const float* g2   = (const float*)d_in[11];
    const float* b2   = (const float*)d_in[12];
    const float* cmk  = (const float*)d_in[13];
    const float* cmr  = (const float*)d_in[14];
    float* out = (float*)d_out;

    __half *ln1h, *XNh, *Hh, *Wtm, *Wcm, *Wcp;
    float *Kb, *Vb, *Rb, *X1, *XN;
    cudaGetSymbolAddress((void**)&ln1h, g_ln1h);
    cudaGetSymbolAddress((void**)&Kb,  g_K);
    cudaGetSymbolAddress((void**)&Vb,  g_V);
    cudaGetSymbolAddress((void**)&Rb,  g_R);
    cudaGetSymbolAddress((void**)&X1,  g_X1);
    cudaGetSymbolAddress((void**)&XN,  g_XN);
    cudaGetSymbolAddress((void**)&XNh, g_XNh);
    cudaGetSymbolAddress((void**)&Hh,  g_Hh);
    cudaGetSymbolAddress((void**)&Wtm, g_Wtm);
    cudaGetSymbolAddress((void**)&Wcm, g_Wcm);
    cudaGetSymbolAddress((void**)&Wcp, g_Wcp);

    static bool attr_done = false;
    if (!attr_done) {
        cudaFuncSetAttribute(gemm_f16_kernel<0>,
            cudaFuncAttributeMaxDynamicSharedMemorySize, SMEM_TOT);
        cudaFuncSetAttribute(gemm_f16_kernel<1>,
            cudaFuncAttributeMaxDynamicSharedMemorySize, SMEM_TOT);
        cudaFuncSetAttribute(gemm_f16_kernel<2>,
            cudaFuncAttributeMaxDynamicSharedMemorySize, SMEM_TOT);
        attr_done = true;
    }

    // 0) transpose + fp16-convert weights: W(K,N) -> Wt(N,K)
    transpose_h<<<dim3(N3/32,  CCH/32), dim3(32,8)>>>(W_tm, Wtm, CCH, N3);
    transpose_h<<<dim3(N4/32,  CCH/32), dim3(32,8)>>>(W_cm, Wcm, CCH, N4);
    transpose_h<<<dim3(CCH/32, N4/32),  dim3(32,8)>>>(W_cp, Wcp, N4, CCH);

    // 1) LN1 -> half
    ln_kernel<<<BT, 256>>>(x, g1, b1, ln1h, nullptr);

    // 2) GEMM1 (16384x1024x3072) + time-mix epilogue -> K,V,R (fp32)
    gemm_f16_kernel<0><<<dim3(N3/BN, BT/128), 256, SMEM_TOT>>>(
        ln1h, Wtm, CCH, N3, x, nullptr, tmk, tmv, tmr, Kb, Vb, Rb);

    // 3) WKV scan + residual -> X1, new_state into d_out tail
    wkv_kernel<<<BB * (CCH/32), 32>>>(td, tfst, Kb, Vb, Rb, x, X1,
                                      out + (size_t)BT * CCH);

    // 4) LN2 -> half (GEMM input) + fp32 (final epilogue)
    ln_kernel<<<BT, 256>>>(X1, g2, b2, XNh, XN);

    // 5) GEMM2 (16384x1024x4096) + channel-mix + relu^2 -> H (half)
    gemm_f16_kernel<1><<<dim3(N4/BN, BT/128), 256, SMEM_TOT>>>(
        XNh, Wcm, CCH, N4, X1, nullptr, cmk, nullptr, nullptr,
        (float*)Hh, nullptr, nullptr);

    // 6) GEMM3 (16384x4096x1024) + final residual -> d_out
    gemm_f16_kernel<2><<<dim3(CCH/BN, BT/128), 256, SMEM_TOT>>>(
        Hh, Wcp, N4, CCH, X1, XN, cmr, nullptr, nullptr,
        out, nullptr, nullptr);
}